// round 7
// baseline (speedup 1.0000x reference)
#include <cuda_runtime.h>
#include <cuda_bf16.h>
#include <cstdint>
#include <math.h>

#define BB 4
#define TT 4096
#define EE 1024
#define DD 64
#define MM (BB*TT)

// ---------------------------------------------------------------------------
// Device scratch
// ---------------------------------------------------------------------------
__device__ __nv_bfloat16 g_qhi[MM*DD];
__device__ __nv_bfloat16 g_qlo[MM*DD];
__device__ __nv_bfloat16 g_khi[MM*DD];
__device__ __nv_bfloat16 g_klo[MM*DD];
__device__ __nv_bfloat16 g_vthi[MM*DD];
__device__ __nv_bfloat16 g_vtlo[MM*DD];

#define WCHUNK_BYTES (192*128)
__device__ unsigned char g_whi[16*WCHUNK_BYTES];
__device__ unsigned char g_wlo[16*WCHUNK_BYTES];

__device__ unsigned char g_xhi[(size_t)MM*16*128];
__device__ unsigned char g_xlo[(size_t)MM*16*128];

// ---------------------------------------------------------------------------
// Helpers
// ---------------------------------------------------------------------------
#define DEVINL __device__ __forceinline__

DEVINL uint32_t smem_u32(const void* p) {
    uint32_t a;
    asm("{ .reg .u64 t; cvta.to.shared.u64 t, %1; cvt.u32.u64 %0, t; }"
        : "=r"(a) : "l"(p));
    return a;
}

#define SWZ128(o) ((o) ^ (((o) >> 3) & 0x70))

#define CP_ASYNC16(dst, src) \
    asm volatile("cp.async.cg.shared.global [%0], [%1], 16;" \
                 :: "r"(dst), "l"(src) : "memory")
#define CP_COMMIT() asm volatile("cp.async.commit_group;" ::: "memory")
#define CP_WAIT0()  asm volatile("cp.async.wait_group 0;"  ::: "memory")

#define NB_SYNC(id) asm volatile("bar.sync %0, 128;" :: "r"(id) : "memory")

DEVINL uint32_t pack_bf16x2(__nv_bfloat16 a, __nv_bfloat16 b) {
    return (uint32_t)__bfloat16_as_ushort(a) |
           ((uint32_t)__bfloat16_as_ushort(b) << 16);
}
DEVINL void split_bf16(float x, __nv_bfloat16& h, __nv_bfloat16& l) {
    h = __float2bfloat16(x);
    l = __float2bfloat16(x - __bfloat162float(h));
}

DEVINL void ldsm_x4(uint32_t r[4], uint32_t addr) {
    asm volatile("ldmatrix.sync.aligned.m8n8.x4.shared.b16 {%0,%1,%2,%3}, [%4];"
        : "=r"(r[0]), "=r"(r[1]), "=r"(r[2]), "=r"(r[3]) : "r"(addr));
}
DEVINL void ldsm_x2(uint32_t r[2], uint32_t addr) {
    asm volatile("ldmatrix.sync.aligned.m8n8.x2.shared.b16 {%0,%1}, [%2];"
        : "=r"(r[0]), "=r"(r[1]) : "r"(addr));
}
DEVINL void mma16816(float c[4], const uint32_t a[4], const uint32_t b[2]) {
    asm volatile(
        "mma.sync.aligned.m16n8k16.row.col.f32.bf16.bf16.f32 "
        "{%0,%1,%2,%3}, {%4,%5,%6,%7}, {%8,%9}, {%0,%1,%2,%3};"
        : "+f"(c[0]), "+f"(c[1]), "+f"(c[2]), "+f"(c[3])
        : "r"(a[0]), "r"(a[1]), "r"(a[2]), "r"(a[3]), "r"(b[0]), "r"(b[1]));
}

// ---------------------------------------------------------------------------
// Merged prep: blocks < 8192 split X; blocks >= 8192 split/transpose W.
// ---------------------------------------------------------------------------
__global__ __launch_bounds__(256) void prep(
    const float* __restrict__ X,
    const float* __restrict__ Wq, const float* __restrict__ Wk,
    const float* __restrict__ Wv)
{
    if (blockIdx.x < 8192) {
        const int u = blockIdx.x * 256 + threadIdx.x;
        const int row  = u >> 7;
        const int unit = u & 127;
        const int c    = unit >> 3;
        const int col8 = unit & 7;
        const float4 a = *(const float4*)&X[(size_t)row * EE + c * 64 + col8 * 8];
        const float4 b = *(const float4*)&X[(size_t)row * EE + c * 64 + col8 * 8 + 4];
        __nv_bfloat16 h0,l0,h1,l1,h2,l2,h3,l3,h4,l4,h5,l5,h6,l6,h7,l7;
        split_bf16(a.x, h0, l0); split_bf16(a.y, h1, l1);
        split_bf16(a.z, h2, l2); split_bf16(a.w, h3, l3);
        split_bf16(b.x, h4, l4); split_bf16(b.y, h5, l5);
        split_bf16(b.z, h6, l6); split_bf16(b.w, h7, l7);
        uint4 hh = make_uint4(pack_bf16x2(h0,h1), pack_bf16x2(h2,h3),
                              pack_bf16x2(h4,h5), pack_bf16x2(h6,h7));
        uint4 ll = make_uint4(pack_bf16x2(l0,l1), pack_bf16x2(l2,l3),
                              pack_bf16x2(l4,l5), pack_bf16x2(l6,l7));
        size_t off = (((size_t)row * 16 + c) << 7)
                   + ((((uint32_t)col8 * 16) ^ ((uint32_t)(row & 7) << 4)));
        *(uint4*)(g_xhi + off) = hh;
        *(uint4*)(g_xlo + off) = ll;
    } else {
        const int c = blockIdx.x - 8192;
        for (int it = threadIdx.x; it < 1536; it += 256) {
            int n = it % 192;
            int g = it / 192;
            int mat = n >> 6, d = n & 63;
            const float* Wm = (mat == 0) ? Wq : (mat == 1) ? Wk : Wv;
            int kk0 = g * 8;
            uint32_t hi[4], lo[4];
#pragma unroll
            for (int j = 0; j < 4; j++) {
                __nv_bfloat16 h0, l0, h1, l1;
                split_bf16(Wm[(size_t)(c*64 + kk0 + 2*j    ) * 64 + d], h0, l0);
                split_bf16(Wm[(size_t)(c*64 + kk0 + 2*j + 1) * 64 + d], h1, l1);
                hi[j] = pack_bf16x2(h0, h1);
                lo[j] = pack_bf16x2(l0, l1);
            }
            uint32_t sw = SWZ128((uint32_t)n * 128 + (uint32_t)kk0 * 2);
            *(uint4*)(g_whi + (size_t)c * WCHUNK_BYTES + sw) = make_uint4(hi[0], hi[1], hi[2], hi[3]);
            *(uint4*)(g_wlo + (size_t)c * WCHUNK_BYTES + sw) = make_uint4(lo[0], lo[1], lo[2], lo[3]);
        }
    }
}

// ---------------------------------------------------------------------------
// QKV via mma.sync (unchanged — at HMMA floor)
// ---------------------------------------------------------------------------
#define QB_A_HI 0
#define QB_A_LO 8192
#define QB_B_HI 16384
#define QB_B_LO 40960
#define QB_STRIDE 65536
#define QKV_SMEM (2*QB_STRIDE)

__global__ __launch_bounds__(256, 1) void qkv_mma(
    const float* __restrict__ bq, const float* __restrict__ bk,
    const float* __restrict__ bv)
{
    extern __shared__ __align__(1024) unsigned char sm[];
    const uint32_t sb = smem_u32(sm);
    const int tid  = threadIdx.x;
    const int warp = tid >> 5;
    const int lane = tid & 31;
    const int m0   = blockIdx.x * 64;
    const int wbase = warp * 24;

    const int rA = (lane & 7) | (((lane >> 3) & 1) << 3);
    const int uA = lane >> 4;
    const int rB = lane & 7;
    const int uB = (lane >> 3) & 1;
    const uint32_t swA = (uint32_t)(rA & 7) << 4;
    const uint32_t swB = (uint32_t)(rB & 7) << 4;

    float acc[4][3][4];
#pragma unroll
    for (int mt = 0; mt < 4; mt++)
#pragma unroll
        for (int nt = 0; nt < 3; nt++)
#pragma unroll
            for (int i = 0; i < 4; i++) acc[mt][nt][i] = 0.f;

    {
#pragma unroll
        for (int j = 0; j < 6; j++) {
            int f = tid + 256 * j;
            CP_ASYNC16(sb + QB_B_HI + f * 16, g_whi + (size_t)f * 16);
            CP_ASYNC16(sb + QB_B_LO + f * 16, g_wlo + (size_t)f * 16);
        }
#pragma unroll
        for (int i = 0; i < 4; i++) {
            int u = tid + 256 * i;
            int mat = u >> 9, w = u & 511;
            size_t src = (((size_t)(m0 + (w >> 3)) * 16) << 7) + (w & 7) * 16;
            const unsigned char* sp = (mat ? g_xlo : g_xhi) + src;
            CP_ASYNC16(sb + (mat ? QB_A_LO : QB_A_HI) + (uint32_t)w * 16, sp);
        }
        CP_COMMIT();
        CP_WAIT0();
        __syncthreads();
    }

    for (int c = 0; c < 16; c++) {
        const uint32_t bufc = sb + (uint32_t)(c & 1) * QB_STRIDE;
        const uint32_t bufn = sb + (uint32_t)((c + 1) & 1) * QB_STRIDE;
        const bool hasNext = (c < 15);

        if (hasNext) {
            const unsigned char* wh = g_whi + (size_t)(c + 1) * WCHUNK_BYTES;
            const unsigned char* wl = g_wlo + (size_t)(c + 1) * WCHUNK_BYTES;
#pragma unroll
            for (int j = 0; j < 6; j++) {
                int f = tid + 256 * j;
                CP_ASYNC16(bufn + QB_B_HI + f * 16, wh + (size_t)f * 16);
                CP_ASYNC16(bufn + QB_B_LO + f * 16, wl + (size_t)f * 16);
            }
#pragma unroll
            for (int i = 0; i < 4; i++) {
                int u = tid + 256 * i;
                int mat = u >> 9, w = u & 511;
                size_t src = (((size_t)(m0 + (w >> 3)) * 16 + (c + 1)) << 7) + (w & 7) * 16;
                const unsigned char* sp = (mat ? g_xlo : g_xhi) + src;
                CP_ASYNC16(bufn + (mat ? QB_A_LO : QB_A_HI) + (uint32_t)w * 16, sp);
            }
            CP_COMMIT();
        }

#pragma unroll
        for (int kk = 0; kk < 4; kk++) {
            uint32_t ah[4][4], al[4][4];
#pragma unroll
            for (int mt = 0; mt < 4; mt++) {
                uint32_t ra = bufc + QB_A_HI + (uint32_t)(16*mt + rA) * 128
                            + (((uint32_t)(2*kk + uA) * 16) ^ swA);
                ldsm_x4(ah[mt], ra);
                ldsm_x4(al[mt], ra + (QB_A_LO - QB_A_HI));
            }
            uint32_t bh[3][2], bl[3][2];
#pragma unroll
            for (int nt = 0; nt < 3; nt++) {
                uint32_t rb = bufc + QB_B_HI + (uint32_t)(wbase + 8*nt + rB) * 128
                            + (((uint32_t)(2*kk + uB) * 16) ^ swB);
                ldsm_x2(bh[nt], rb);
                ldsm_x2(bl[nt], rb + (QB_B_LO - QB_B_HI));
            }
#pragma unroll
            for (int mt = 0; mt < 4; mt++)
#pragma unroll
                for (int nt = 0; nt < 3; nt++)
                    mma16816(acc[mt][nt], ah[mt], bh[nt]);
#pragma unroll
            for (int mt = 0; mt < 4; mt++)
#pragma unroll
                for (int nt = 0; nt < 3; nt++)
                    mma16816(acc[mt][nt], ah[mt], bl[nt]);
#pragma unroll
            for (int mt = 0; mt < 4; mt++)
#pragma unroll
                for (int nt = 0; nt < 3; nt++)
                    mma16816(acc[mt][nt], al[mt], bh[nt]);
        }

        CP_WAIT0();
        __syncthreads();
    }

    const int gid = lane >> 2, tig = lane & 3;
#pragma unroll
    for (int mt = 0; mt < 4; mt++) {
#pragma unroll
        for (int nt = 0; nt < 3; nt++) {
            const int col0 = wbase + 8 * nt;
            const int mat  = col0 >> 6;
            const int d0   = (col0 & 63) + 2 * tig;
            const float* bp = (mat == 0) ? bq : (mat == 1) ? bk : bv;
            const float b0v = bp[d0], b1v = bp[d0 + 1];
            const int row0 = m0 + 16 * mt + gid;
            float v00 = acc[mt][nt][0] + b0v, v01 = acc[mt][nt][1] + b1v;
            float v10 = acc[mt][nt][2] + b0v, v11 = acc[mt][nt][3] + b1v;
            __nv_bfloat16 h00,l00,h01,l01,h10,l10,h11,l11;
            split_bf16(v00, h00, l00); split_bf16(v01, h01, l01);
            split_bf16(v10, h10, l10); split_bf16(v11, h11, l11);
            if (mat < 2) {
                __nv_bfloat16* dh = mat ? g_khi : g_qhi;
                __nv_bfloat16* dl = mat ? g_klo : g_qlo;
                *(uint32_t*)&dh[(size_t)row0 * DD + d0]       = pack_bf16x2(h00, h01);
                *(uint32_t*)&dl[(size_t)row0 * DD + d0]       = pack_bf16x2(l00, l01);
                *(uint32_t*)&dh[(size_t)(row0 + 8) * DD + d0] = pack_bf16x2(h10, h11);
                *(uint32_t*)&dl[(size_t)(row0 + 8) * DD + d0] = pack_bf16x2(l10, l11);
            } else {
                const int bb = row0 >> 12, t = row0 & 4095;
                size_t r0o = ((size_t)bb * 64 + d0) * TT + t;
                size_t r1o = ((size_t)bb * 64 + d0 + 1) * TT + t;
                g_vthi[r0o]     = h00;  g_vtlo[r0o]     = l00;
                g_vthi[r1o]     = h01;  g_vtlo[r1o]     = l01;
                g_vthi[r0o + 8] = h10;  g_vtlo[r0o + 8] = l10;
                g_vthi[r1o + 8] = h11;  g_vtlo[r1o + 8] = l11;
            }
        }
    }
}

// ---------------------------------------------------------------------------
// Flash attention: paired halves; delayed-PV pipeline (PV_{j-1} overlaps
// softmax_j); V 3-ring, K 2-ring; ldsm_x4 B-operands.
// Per half: Q 16K @0, K stages @16384+(s*16384), V stages @49152+(s*16384).
// ---------------------------------------------------------------------------
#define AH_STRIDE 98304
#define ATTN_SMEM (2*AH_STRIDE)   // 196608

DEVINL void stage_k(uint32_t dst, int htid, int b, int t0) {
#pragma unroll
    for (int i = 0; i < 8; i++) {
        int u = htid + 128 * i;                // 0..1023
        int mat = u >> 9, w = u & 511, r = w >> 3, cu = w & 7;
        const __nv_bfloat16* src = (mat ? g_klo : g_khi)
                                 + (size_t)(b * TT + t0 + r) * DD + cu * 8;
        uint32_t d = dst + mat * 8192 + (uint32_t)r * 128
                   + (((uint32_t)cu * 16) ^ ((uint32_t)(r & 7) << 4));
        CP_ASYNC16(d, src);
    }
}
DEVINL void stage_v(uint32_t dst, int htid, int b, int t0) {
#pragma unroll
    for (int i = 0; i < 8; i++) {
        int u = htid + 128 * i;
        int mat = u >> 9, w = u & 511, r = w >> 3, cu = w & 7;
        const __nv_bfloat16* src = (mat ? g_vtlo : g_vthi)
                                 + ((size_t)b * DD + r) * TT + t0 + cu * 8;
        uint32_t d = dst + mat * 8192 + (uint32_t)r * 128
                   + (((uint32_t)cu * 16) ^ ((uint32_t)(r & 7) << 4));
        CP_ASYNC16(d, src);
    }
}

// PV accumulation: O += Phi*Vhi + Plo*Vhi + Phi*Vlo  (order matches R6)
DEVINL void pv_accum(float oA[8][4], const uint32_t pHi[4][4], const uint32_t pLo[4][4],
                     uint32_t vbase, int rowB4, int uB, uint32_t swB) {
#pragma unroll
    for (int kk = 0; kk < 4; kk++) {
        uint32_t vh[4][4];
#pragma unroll
        for (int p = 0; p < 4; p++) {
            uint32_t rv = vbase + (uint32_t)(p * 16 + rowB4) * 128
                        + (((uint32_t)(2*kk + uB) * 16) ^ swB);
            ldsm_x4(vh[p], rv);
        }
#pragma unroll
        for (int p = 0; p < 4; p++) {
            mma16816(oA[2*p],   pHi[kk], vh[p]);
            mma16816(oA[2*p+1], pHi[kk], vh[p] + 2);
        }
#pragma unroll
        for (int p = 0; p < 4; p++) {
            mma16816(oA[2*p],   pLo[kk], vh[p]);
            mma16816(oA[2*p+1], pLo[kk], vh[p] + 2);
        }
        uint32_t vl[4][4];
#pragma unroll
        for (int p = 0; p < 4; p++) {
            uint32_t rv = vbase + 8192 + (uint32_t)(p * 16 + rowB4) * 128
                        + (((uint32_t)(2*kk + uB) * 16) ^ swB);
            ldsm_x4(vl[p], rv);
        }
#pragma unroll
        for (int p = 0; p < 4; p++) {
            mma16816(oA[2*p],   pHi[kk], vl[p]);
            mma16816(oA[2*p+1], pHi[kk], vl[p] + 2);
        }
    }
}

__global__ __launch_bounds__(256, 1) void attn_mma(float* __restrict__ out)
{
    extern __shared__ __align__(1024) unsigned char sm[];
    const uint32_t sb = smem_u32(sm);
    const int tid  = threadIdx.x;
    const int warp = tid >> 5;
    const int lane = tid & 31;
    const int half = warp >> 2;
    const int wh   = warp & 3;
    const int htid = tid & 127;
    const int b    = blockIdx.y;
    const int qp   = blockIdx.x;
    const int qt   = half ? (63 - qp) : qp;
    const uint32_t hb = sb + (uint32_t)half * AH_STRIDE;
    const int tok0 = b * TT + qt * 64;
    const int nbid = half + 1;

    const int gid = lane >> 2, tig = lane & 3;
    const int rA = (lane & 7) | (((lane >> 3) & 1) << 3);
    const int uA = lane >> 4;
    const int uB = (lane >> 3) & 1;
    const uint32_t swA = (uint32_t)(rA & 7) << 4;
    const uint32_t swB = (uint32_t)(lane & 7) << 4;
    const int rowB4 = ((lane >> 4) << 3) + (lane & 7);   // x4 row-within-pair

    // ---- prologue: stage Q + K0 + V0 ----
#pragma unroll
    for (int i = 0; i < 8; i++) {
        int u = htid + 128 * i;
        int matq = u >> 9, r = (u >> 3) & 63, cu = u & 7;
        const __nv_bfloat16* src = (matq ? g_qlo : g_qhi)
                                 + (size_t)(tok0 + r) * DD + cu * 8;
        uint32_t dst = hb + matq * 8192 + (uint32_t)r * 128
                     + (((uint32_t)cu * 16) ^ ((uint32_t)(r & 7) << 4));
        CP_ASYNC16(dst, src);
    }
    stage_k(hb + 16384, htid, b, 0);
    stage_v(hb + 49152, htid, b, 0);
    CP_COMMIT();
    CP_WAIT0();
    NB_SYNC(nbid);

    // ---- hoist Q fragments ----
    uint32_t qh[4][4], ql[4][4];
#pragma unroll
    for (int kk = 0; kk < 4; kk++) {
        uint32_t ra = hb + (uint32_t)(wh * 16 + rA) * 128
                    + (((uint32_t)(2*kk + uA) * 16) ^ swA);
        ldsm_x4(qh[kk], ra);
        ldsm_x4(ql[kk], ra + 8192);
    }

    float oA[8][4];
#pragma unroll
    for (int nd = 0; nd < 8; nd++)
#pragma unroll
        for (int i = 0; i < 4; i++) oA[nd][i] = 0.f;
    float m0r = -3.0e38f, m1r = -3.0e38f, l0r = 0.f, l1r = 0.f;
    uint32_t pHi[4][4], pLo[4][4];
    int svN = 1;   // V prefetch stage for iter 0 -> (0+1)%3
    int svP = 2;   // V stage for PV_{j-1} at j=0 (unused), becomes (j-1)%3

    for (int j = 0; j <= qt; j++) {
        if (j) { CP_WAIT0(); NB_SYNC(nbid); }

        if (j < qt) {   // prefetch AFTER barrier: targets are provably dead
            stage_k(hb + 16384 + (uint32_t)((j + 1) & 1) * 16384, htid, b, (j + 1) * 64);
            stage_v(hb + 49152 + (uint32_t)svN * 16384, htid, b, (j + 1) * 64);
            CP_COMMIT();
        }
        const uint32_t kbase = hb + 16384 + (uint32_t)(j & 1) * 16384;

        // ---- S_j = Q . K^T  (qh*kh, ql*kh, qh*kl per accumulator) ----
        float sA[8][4];
#pragma unroll
        for (int nt = 0; nt < 8; nt++)
#pragma unroll
            for (int i = 0; i < 4; i++) sA[nt][i] = 0.f;
#pragma unroll
        for (int kk = 0; kk < 4; kk++) {
            uint32_t kh[4][4];
#pragma unroll
            for (int p = 0; p < 4; p++) {
                uint32_t rb = kbase + (uint32_t)(p * 16 + rowB4) * 128
                            + (((uint32_t)(2*kk + uB) * 16) ^ swB);
                ldsm_x4(kh[p], rb);
            }
#pragma unroll
            for (int p = 0; p < 4; p++) {
                mma16816(sA[2*p],   qh[kk], kh[p]);
                mma16816(sA[2*p+1], qh[kk], kh[p] + 2);
            }
#pragma unroll
            for (int p = 0; p < 4; p++) {
                mma16816(sA[2*p],   ql[kk], kh[p]);
                mma16816(sA[2*p+1], ql[kk], kh[p] + 2);
            }
            uint32_t kl[4][4];
#pragma unroll
            for (int p = 0; p < 4; p++) {
                uint32_t rb = kbase + 8192 + (uint32_t)(p * 16 + rowB4) * 128
                            + (((uint32_t)(2*kk + uB) * 16) ^ swB);
                ldsm_x4(kl[p], rb);
            }
#pragma unroll
            for (int p = 0; p < 4; p++) {
                mma16816(sA[2*p],   qh[kk], kl[p]);
                mma16816(sA[2*p+1], qh[kk], kl[p] + 2);
            }
        }

        // ---- scale + causal mask ----
        if (j == qt) {
            const int r0 = qt * 64 + wh * 16 + gid, r1 = r0 + 8;
#pragma unroll
            for (int nt = 0; nt < 8; nt++) {
                int c0 = j * 64 + nt * 8 + 2 * tig;
                sA[nt][0] = (c0     <= r0) ? sA[nt][0] * 0.125f : -1e30f;
                sA[nt][1] = (c0 + 1 <= r0) ? sA[nt][1] * 0.125f : -1e30f;
                sA[nt][2] = (c0     <= r1) ? sA[nt][2] * 0.125f : -1e30f;
                sA[nt][3] = (c0 + 1 <= r1) ? sA[nt][3] * 0.125f : -1e30f;
            }
        } else {
#pragma unroll
            for (int nt = 0; nt < 8; nt++)
#pragma unroll
                for (int i = 0; i < 4; i++) sA[nt][i] *= 0.125f;
        }

        // ---- row max + alpha (chains) ----
        float mx0 = sA[0][0], mx1 = sA[0][2];
#pragma unroll
        for (int nt = 0; nt < 8; nt++) {
            mx0 = fmaxf(mx0, fmaxf(sA[nt][0], sA[nt][1]));
            mx1 = fmaxf(mx1, fmaxf(sA[nt][2], sA[nt][3]));
        }
        mx0 = fmaxf(mx0, __shfl_xor_sync(0xffffffffu, mx0, 1));
        mx0 = fmaxf(mx0, __shfl_xor_sync(0xffffffffu, mx0, 2));
        mx1 = fmaxf(mx1, __shfl_xor_sync(0xffffffffu, mx1, 1));
        mx1 = fmaxf(mx1, __shfl_xor_sync(0xffffffffu, mx1, 2));
        float mn0 = fmaxf(m0r, mx0), mn1 = fmaxf(m1r, mx1);
        float al0 = __expf(m0r - mn0), al1 = __expf(m1r - mn1);

        // ---- PV_{j-1}: independent MMA stream overlapping softmax chains ----
        if (j) pv_accum(oA, pHi, pLo, hb + 49152 + (uint32_t)svP * 16384,
                        rowB4, uB, swB);

        // ---- exp + row sums ----
        float ps0 = 0.f, ps1 = 0.f;
#pragma unroll
        for (int nt = 0; nt < 8; nt++) {
            sA[nt][0] = __expf(sA[nt][0] - mn0);
            sA[nt][1] = __expf(sA[nt][1] - mn0);
            sA[nt][2] = __expf(sA[nt][2] - mn1);
            sA[nt][3] = __expf(sA[nt][3] - mn1);
            ps0 += sA[nt][0] + sA[nt][1];
            ps1 += sA[nt][2] + sA[nt][3];
        }
        ps0 += __shfl_xor_sync(0xffffffffu, ps0, 1);
        ps0 += __shfl_xor_sync(0xffffffffu, ps0, 2);
        ps1 += __shfl_xor_sync(0xffffffffu, ps1, 1);
        ps1 += __shfl_xor_sync(0xffffffffu, ps1, 2);
        l0r = l0r * al0 + ps0;  m0r = mn0;
        l1r = l1r * al1 + ps1;  m1r = mn1;

        // ---- O rescale AFTER PV_{j-1} add (D = (D + P_{j-1}V_{j-1})*alpha_j) ----
#pragma unroll
        for (int nd = 0; nd < 8; nd++) {
            oA[nd][0] *= al0; oA[nd][1] *= al0;
            oA[nd][2] *= al1; oA[nd][3] *= al1;
        }

        // ---- split P_j into bf16 fragments for next iteration ----
#pragma unroll
        for (int kk = 0; kk < 4; kk++) {
            __nv_bfloat16 h0,l0,h1,l1;
            split_bf16(sA[2*kk][0], h0, l0);   split_bf16(sA[2*kk][1], h1, l1);
            pHi[kk][0] = pack_bf16x2(h0, h1);  pLo[kk][0] = pack_bf16x2(l0, l1);
            split_bf16(sA[2*kk][2], h0, l0);   split_bf16(sA[2*kk][3], h1, l1);
            pHi[kk][1] = pack_bf16x2(h0, h1);  pLo[kk][1] = pack_bf16x2(l0, l1);
            split_bf16(sA[2*kk+1][0], h0, l0); split_bf16(sA[2*kk+1][1], h1, l1);
            pHi[kk][2] = pack_bf16x2(h0, h1);  pLo[kk][2] = pack_bf16x2(l0, l1);
            split_bf16(sA[2*kk+1][2], h0, l0); split_bf16(sA[2*kk+1][3], h1, l1);
            pHi[kk][3] = pack_bf16x2(h0, h1);  pLo[kk][3] = pack_bf16x2(l0, l1);
        }

        svN = (svN == 2) ? 0 : svN + 1;
        svP = (svP == 2) ? 0 : svP + 1;
    }

    // ---- drain: PV_{qt} (svP now == qt%3) ----
    pv_accum(oA, pHi, pLo, hb + 49152 + (uint32_t)svP * 16384, rowB4, uB, swB);

    // ---- epilogue ----
    const float inv0 = 1.f / l0r, inv1 = 1.f / l1r;
    const size_t out0 = ((size_t)b * TT + qt * 64 + wh * 16 + gid) * DD;
    const size_t out1 = out0 + 8 * DD;
#pragma unroll
    for (int nd = 0; nd < 8; nd++) {
        const int d0 = nd * 8 + 2 * tig;
        *(float2*)&out[out0 + d0] = make_float2(oA[nd][0] * inv0, oA[nd][1] * inv0);
        *(float2*)&out[out1 + d0] = make_float2(oA[nd][2] * inv1, oA[nd][3] * inv1);
    }
}

// ---------------------------------------------------------------------------
extern "C" void kernel_launch(void* const* d_in, const int* in_sizes, int n_in,
                              void* d_out, int out_size)
{
    const float* X  = (const float*)d_in[0];
    const float* Wq = (const float*)d_in[1];
    const float* bq = (const float*)d_in[2];
    const float* Wk = (const float*)d_in[3];
    const float* bk = (const float*)d_in[4];
    const float* Wv = (const float*)d_in[5];
    const float* bv = (const float*)d_in[6];
    float* out = (float*)d_out;

    prep<<<8192 + 16, 256>>>(X, Wq, Wk, Wv);

    cudaFuncSetAttribute(qkv_mma, cudaFuncAttributeMaxDynamicSharedMemorySize, QKV_SMEM);
    qkv_mma<<<MM / 64, 256, QKV_SMEM>>>(bq, bk, bv);

    cudaFuncSetAttribute(attn_mma, cudaFuncAttributeMaxDynamicSharedMemorySize, ATTN_SMEM);
    attn_mma<<<dim3(32, BB), 256, ATTN_SMEM>>>(out);
}

// round 8
// speedup vs baseline: 1.1326x; 1.1326x over previous
#include <cuda_runtime.h>
#include <cuda_bf16.h>
#include <cstdint>
#include <math.h>

#define BB 4
#define TT 4096
#define EE 1024
#define DD 64
#define MM (BB*TT)

// ---------------------------------------------------------------------------
// Device scratch
// ---------------------------------------------------------------------------
__device__ __nv_bfloat16 g_qhi[MM*DD];
__device__ __nv_bfloat16 g_qlo[MM*DD];
__device__ __nv_bfloat16 g_khi[MM*DD];
__device__ __nv_bfloat16 g_klo[MM*DD];
__device__ __nv_bfloat16 g_vthi[MM*DD];
__device__ __nv_bfloat16 g_vtlo[MM*DD];

#define WCHUNK_BYTES (192*128)
__device__ unsigned char g_whi[16*WCHUNK_BYTES];
__device__ unsigned char g_wlo[16*WCHUNK_BYTES];

__device__ unsigned char g_xhi[(size_t)MM*16*128];
__device__ unsigned char g_xlo[(size_t)MM*16*128];

// ---------------------------------------------------------------------------
// Helpers
// ---------------------------------------------------------------------------
#define DEVINL __device__ __forceinline__

DEVINL uint32_t smem_u32(const void* p) {
    uint32_t a;
    asm("{ .reg .u64 t; cvta.to.shared.u64 t, %1; cvt.u32.u64 %0, t; }"
        : "=r"(a) : "l"(p));
    return a;
}

#define SWZ128(o) ((o) ^ (((o) >> 3) & 0x70))

#define CP_ASYNC16(dst, src) \
    asm volatile("cp.async.cg.shared.global [%0], [%1], 16;" \
                 :: "r"(dst), "l"(src) : "memory")
#define CP_COMMIT() asm volatile("cp.async.commit_group;" ::: "memory")
#define CP_WAIT0()  asm volatile("cp.async.wait_group 0;"  ::: "memory")

#define NB_SYNC(id) asm volatile("bar.sync %0, 128;" :: "r"(id) : "memory")

DEVINL uint32_t pack_bf16x2(__nv_bfloat16 a, __nv_bfloat16 b) {
    return (uint32_t)__bfloat16_as_ushort(a) |
           ((uint32_t)__bfloat16_as_ushort(b) << 16);
}
DEVINL void split_bf16(float x, __nv_bfloat16& h, __nv_bfloat16& l) {
    h = __float2bfloat16(x);
    l = __float2bfloat16(x - __bfloat162float(h));
}

DEVINL void ldsm_x4(uint32_t r[4], uint32_t addr) {
    asm volatile("ldmatrix.sync.aligned.m8n8.x4.shared.b16 {%0,%1,%2,%3}, [%4];"
        : "=r"(r[0]), "=r"(r[1]), "=r"(r[2]), "=r"(r[3]) : "r"(addr));
}
DEVINL void ldsm_x2(uint32_t r[2], uint32_t addr) {
    asm volatile("ldmatrix.sync.aligned.m8n8.x2.shared.b16 {%0,%1}, [%2];"
        : "=r"(r[0]), "=r"(r[1]) : "r"(addr));
}
DEVINL void mma16816(float c[4], const uint32_t a[4], const uint32_t b[2]) {
    asm volatile(
        "mma.sync.aligned.m16n8k16.row.col.f32.bf16.bf16.f32 "
        "{%0,%1,%2,%3}, {%4,%5,%6,%7}, {%8,%9}, {%0,%1,%2,%3};"
        : "+f"(c[0]), "+f"(c[1]), "+f"(c[2]), "+f"(c[3])
        : "r"(a[0]), "r"(a[1]), "r"(a[2]), "r"(a[3]), "r"(b[0]), "r"(b[1]));
}

// ---------------------------------------------------------------------------
// Merged prep: blocks < 8192 split X; blocks >= 8192 split/transpose W.
// ---------------------------------------------------------------------------
__global__ __launch_bounds__(256) void prep(
    const float* __restrict__ X,
    const float* __restrict__ Wq, const float* __restrict__ Wk,
    const float* __restrict__ Wv)
{
    if (blockIdx.x < 8192) {
        const int u = blockIdx.x * 256 + threadIdx.x;
        const int row  = u >> 7;
        const int unit = u & 127;
        const int c    = unit >> 3;
        const int col8 = unit & 7;
        const float4 a = *(const float4*)&X[(size_t)row * EE + c * 64 + col8 * 8];
        const float4 b = *(const float4*)&X[(size_t)row * EE + c * 64 + col8 * 8 + 4];
        __nv_bfloat16 h0,l0,h1,l1,h2,l2,h3,l3,h4,l4,h5,l5,h6,l6,h7,l7;
        split_bf16(a.x, h0, l0); split_bf16(a.y, h1, l1);
        split_bf16(a.z, h2, l2); split_bf16(a.w, h3, l3);
        split_bf16(b.x, h4, l4); split_bf16(b.y, h5, l5);
        split_bf16(b.z, h6, l6); split_bf16(b.w, h7, l7);
        uint4 hh = make_uint4(pack_bf16x2(h0,h1), pack_bf16x2(h2,h3),
                              pack_bf16x2(h4,h5), pack_bf16x2(h6,h7));
        uint4 ll = make_uint4(pack_bf16x2(l0,l1), pack_bf16x2(l2,l3),
                              pack_bf16x2(l4,l5), pack_bf16x2(l6,l7));
        size_t off = (((size_t)row * 16 + c) << 7)
                   + ((((uint32_t)col8 * 16) ^ ((uint32_t)(row & 7) << 4)));
        *(uint4*)(g_xhi + off) = hh;
        *(uint4*)(g_xlo + off) = ll;
    } else {
        const int c = blockIdx.x - 8192;
        for (int it = threadIdx.x; it < 1536; it += 256) {
            int n = it % 192;
            int g = it / 192;
            int mat = n >> 6, d = n & 63;
            const float* Wm = (mat == 0) ? Wq : (mat == 1) ? Wk : Wv;
            int kk0 = g * 8;
            uint32_t hi[4], lo[4];
#pragma unroll
            for (int j = 0; j < 4; j++) {
                __nv_bfloat16 h0, l0, h1, l1;
                split_bf16(Wm[(size_t)(c*64 + kk0 + 2*j    ) * 64 + d], h0, l0);
                split_bf16(Wm[(size_t)(c*64 + kk0 + 2*j + 1) * 64 + d], h1, l1);
                hi[j] = pack_bf16x2(h0, h1);
                lo[j] = pack_bf16x2(l0, l1);
            }
            uint32_t sw = SWZ128((uint32_t)n * 128 + (uint32_t)kk0 * 2);
            *(uint4*)(g_whi + (size_t)c * WCHUNK_BYTES + sw) = make_uint4(hi[0], hi[1], hi[2], hi[3]);
            *(uint4*)(g_wlo + (size_t)c * WCHUNK_BYTES + sw) = make_uint4(lo[0], lo[1], lo[2], lo[3]);
        }
    }
}

// ---------------------------------------------------------------------------
// QKV via mma.sync. Epilogue folds the 1/sqrt(64)=2^-3 score scale into Q
// (exact power-of-two => bit-identical S downstream).
// ---------------------------------------------------------------------------
#define QB_A_HI 0
#define QB_A_LO 8192
#define QB_B_HI 16384
#define QB_B_LO 40960
#define QB_STRIDE 65536
#define QKV_SMEM (2*QB_STRIDE)

__global__ __launch_bounds__(256, 1) void qkv_mma(
    const float* __restrict__ bq, const float* __restrict__ bk,
    const float* __restrict__ bv)
{
    extern __shared__ __align__(1024) unsigned char sm[];
    const uint32_t sb = smem_u32(sm);
    const int tid  = threadIdx.x;
    const int warp = tid >> 5;
    const int lane = tid & 31;
    const int m0   = blockIdx.x * 64;
    const int wbase = warp * 24;

    const int rA = (lane & 7) | (((lane >> 3) & 1) << 3);
    const int uA = lane >> 4;
    const int rB = lane & 7;
    const int uB = (lane >> 3) & 1;
    const uint32_t swA = (uint32_t)(rA & 7) << 4;
    const uint32_t swB = (uint32_t)(rB & 7) << 4;

    float acc[4][3][4];
#pragma unroll
    for (int mt = 0; mt < 4; mt++)
#pragma unroll
        for (int nt = 0; nt < 3; nt++)
#pragma unroll
            for (int i = 0; i < 4; i++) acc[mt][nt][i] = 0.f;

    {
#pragma unroll
        for (int j = 0; j < 6; j++) {
            int f = tid + 256 * j;
            CP_ASYNC16(sb + QB_B_HI + f * 16, g_whi + (size_t)f * 16);
            CP_ASYNC16(sb + QB_B_LO + f * 16, g_wlo + (size_t)f * 16);
        }
#pragma unroll
        for (int i = 0; i < 4; i++) {
            int u = tid + 256 * i;
            int mat = u >> 9, w = u & 511;
            size_t src = (((size_t)(m0 + (w >> 3)) * 16) << 7) + (w & 7) * 16;
            const unsigned char* sp = (mat ? g_xlo : g_xhi) + src;
            CP_ASYNC16(sb + (mat ? QB_A_LO : QB_A_HI) + (uint32_t)w * 16, sp);
        }
        CP_COMMIT();
        CP_WAIT0();
        __syncthreads();
    }

    for (int c = 0; c < 16; c++) {
        const uint32_t bufc = sb + (uint32_t)(c & 1) * QB_STRIDE;
        const uint32_t bufn = sb + (uint32_t)((c + 1) & 1) * QB_STRIDE;
        const bool hasNext = (c < 15);

        if (hasNext) {
            const unsigned char* wh = g_whi + (size_t)(c + 1) * WCHUNK_BYTES;
            const unsigned char* wl = g_wlo + (size_t)(c + 1) * WCHUNK_BYTES;
#pragma unroll
            for (int j = 0; j < 6; j++) {
                int f = tid + 256 * j;
                CP_ASYNC16(bufn + QB_B_HI + f * 16, wh + (size_t)f * 16);
                CP_ASYNC16(bufn + QB_B_LO + f * 16, wl + (size_t)f * 16);
            }
#pragma unroll
            for (int i = 0; i < 4; i++) {
                int u = tid + 256 * i;
                int mat = u >> 9, w = u & 511;
                size_t src = (((size_t)(m0 + (w >> 3)) * 16 + (c + 1)) << 7) + (w & 7) * 16;
                const unsigned char* sp = (mat ? g_xlo : g_xhi) + src;
                CP_ASYNC16(bufn + (mat ? QB_A_LO : QB_A_HI) + (uint32_t)w * 16, sp);
            }
            CP_COMMIT();
        }

#pragma unroll
        for (int kk = 0; kk < 4; kk++) {
            uint32_t ah[4][4], al[4][4];
#pragma unroll
            for (int mt = 0; mt < 4; mt++) {
                uint32_t ra = bufc + QB_A_HI + (uint32_t)(16*mt + rA) * 128
                            + (((uint32_t)(2*kk + uA) * 16) ^ swA);
                ldsm_x4(ah[mt], ra);
                ldsm_x4(al[mt], ra + (QB_A_LO - QB_A_HI));
            }
            uint32_t bh[3][2], bl[3][2];
#pragma unroll
            for (int nt = 0; nt < 3; nt++) {
                uint32_t rb = bufc + QB_B_HI + (uint32_t)(wbase + 8*nt + rB) * 128
                            + (((uint32_t)(2*kk + uB) * 16) ^ swB);
                ldsm_x2(bh[nt], rb);
                ldsm_x2(bl[nt], rb + (QB_B_LO - QB_B_HI));
            }
#pragma unroll
            for (int mt = 0; mt < 4; mt++)
#pragma unroll
                for (int nt = 0; nt < 3; nt++)
                    mma16816(acc[mt][nt], ah[mt], bh[nt]);
#pragma unroll
            for (int mt = 0; mt < 4; mt++)
#pragma unroll
                for (int nt = 0; nt < 3; nt++)
                    mma16816(acc[mt][nt], ah[mt], bl[nt]);
#pragma unroll
            for (int mt = 0; mt < 4; mt++)
#pragma unroll
                for (int nt = 0; nt < 3; nt++)
                    mma16816(acc[mt][nt], al[mt], bh[nt]);
        }

        CP_WAIT0();
        __syncthreads();
    }

    const int gid = lane >> 2, tig = lane & 3;
#pragma unroll
    for (int mt = 0; mt < 4; mt++) {
#pragma unroll
        for (int nt = 0; nt < 3; nt++) {
            const int col0 = wbase + 8 * nt;
            const int mat  = col0 >> 6;
            const int d0   = (col0 & 63) + 2 * tig;
            const float* bp = (mat == 0) ? bq : (mat == 1) ? bk : bv;
            const float b0v = bp[d0], b1v = bp[d0 + 1];
            const int row0 = m0 + 16 * mt + gid;
            float v00 = acc[mt][nt][0] + b0v, v01 = acc[mt][nt][1] + b1v;
            float v10 = acc[mt][nt][2] + b0v, v11 = acc[mt][nt][3] + b1v;
            if (mat == 0) {   // fold score scale into q (exact: *2^-3)
                v00 *= 0.125f; v01 *= 0.125f; v10 *= 0.125f; v11 *= 0.125f;
            }
            __nv_bfloat16 h00,l00,h01,l01,h10,l10,h11,l11;
            split_bf16(v00, h00, l00); split_bf16(v01, h01, l01);
            split_bf16(v10, h10, l10); split_bf16(v11, h11, l11);
            if (mat < 2) {
                __nv_bfloat16* dh = mat ? g_khi : g_qhi;
                __nv_bfloat16* dl = mat ? g_klo : g_qlo;
                *(uint32_t*)&dh[(size_t)row0 * DD + d0]       = pack_bf16x2(h00, h01);
                *(uint32_t*)&dl[(size_t)row0 * DD + d0]       = pack_bf16x2(l00, l01);
                *(uint32_t*)&dh[(size_t)(row0 + 8) * DD + d0] = pack_bf16x2(h10, h11);
                *(uint32_t*)&dl[(size_t)(row0 + 8) * DD + d0] = pack_bf16x2(l10, l11);
            } else {
                const int bb = row0 >> 12, t = row0 & 4095;
                size_t r0o = ((size_t)bb * 64 + d0) * TT + t;
                size_t r1o = ((size_t)bb * 64 + d0 + 1) * TT + t;
                g_vthi[r0o]     = h00;  g_vtlo[r0o]     = l00;
                g_vthi[r1o]     = h01;  g_vtlo[r1o]     = l01;
                g_vthi[r0o + 8] = h10;  g_vtlo[r0o + 8] = l10;
                g_vthi[r1o + 8] = h11;  g_vtlo[r1o + 8] = l11;
            }
        }
    }
}

// ---------------------------------------------------------------------------
// Flash attention (R6 structure — best measured): paired halves, double-
// buffered KV, term-major MMA issue. Score scale pre-folded into Q.
// ---------------------------------------------------------------------------
#define AH_STRIDE 81920
#define ATTN_SMEM (2*AH_STRIDE)

DEVINL void stage_kv(uint32_t dstbase, int htid, int b, int t0) {
#pragma unroll
    for (int i = 0; i < 16; i++) {
        int u = htid + 128 * i;
        int mat = u >> 9, w = u & 511, r = w >> 3, cu = w & 7;
        const __nv_bfloat16* src;
        if (mat == 0)      src = g_khi  + (size_t)(b * TT + t0 + r) * DD + cu * 8;
        else if (mat == 1) src = g_klo  + (size_t)(b * TT + t0 + r) * DD + cu * 8;
        else if (mat == 2) src = g_vthi + ((size_t)b * DD + r) * TT + t0 + cu * 8;
        else               src = g_vtlo + ((size_t)b * DD + r) * TT + t0 + cu * 8;
        uint32_t dst = dstbase + mat * 8192 + (uint32_t)r * 128
                     + (((uint32_t)cu * 16) ^ ((uint32_t)(r & 7) << 4));
        CP_ASYNC16(dst, src);
    }
}

__global__ __launch_bounds__(256, 1) void attn_mma(float* __restrict__ out)
{
    extern __shared__ __align__(1024) unsigned char sm[];
    const uint32_t sb = smem_u32(sm);
    const int tid  = threadIdx.x;
    const int warp = tid >> 5;
    const int lane = tid & 31;
    const int half = warp >> 2;
    const int wh   = warp & 3;
    const int htid = tid & 127;
    const int b    = blockIdx.y;
    const int qp   = blockIdx.x;
    const int qt   = half ? (63 - qp) : qp;
    const uint32_t hb = sb + (uint32_t)half * AH_STRIDE;
    const int tok0 = b * TT + qt * 64;
    const int nbid = half + 1;

    const int gid = lane >> 2, tig = lane & 3;
    const int rA = (lane & 7) | (((lane >> 3) & 1) << 3);
    const int uA = lane >> 4;
    const int rB = lane & 7;
    const int uB = (lane >> 3) & 1;
    const uint32_t swA = (uint32_t)(rA & 7) << 4;
    const uint32_t swB = (uint32_t)(rB) << 4;

#pragma unroll
    for (int i = 0; i < 8; i++) {
        int u = htid + 128 * i;
        int matq = u >> 9, r = (u >> 3) & 63, cu = u & 7;
        const __nv_bfloat16* src = (matq ? g_qlo : g_qhi)
                                 + (size_t)(tok0 + r) * DD + cu * 8;
        uint32_t dst = hb + matq * 8192 + (uint32_t)r * 128
                     + (((uint32_t)cu * 16) ^ ((uint32_t)(r & 7) << 4));
        CP_ASYNC16(dst, src);
    }
    stage_kv(hb + 16384, htid, b, 0);
    CP_COMMIT();
    CP_WAIT0();
    NB_SYNC(nbid);

    uint32_t qh[4][4], ql[4][4];
#pragma unroll
    for (int kk = 0; kk < 4; kk++) {
        uint32_t ra = hb + (uint32_t)(wh * 16 + rA) * 128
                    + (((uint32_t)(2*kk + uA) * 16) ^ swA);
        ldsm_x4(qh[kk], ra);
        ldsm_x4(ql[kk], ra + 8192);
    }

    float oA[8][4];
#pragma unroll
    for (int nd = 0; nd < 8; nd++)
#pragma unroll
        for (int i = 0; i < 4; i++) oA[nd][i] = 0.f;
    float m0r = -3.0e38f, m1r = -3.0e38f, l0r = 0.f, l1r = 0.f;

    for (int j = 0; j <= qt; j++) {
        if (j) { CP_WAIT0(); NB_SYNC(nbid); }
        const uint32_t buf = hb + 16384 + (uint32_t)(j & 1) * 32768;

        if (j < qt) {
            stage_kv(hb + 16384 + (uint32_t)((j + 1) & 1) * 32768, htid, b, (j + 1) * 64);
            CP_COMMIT();
        }

        // ---- S = Q . K^T (q pre-scaled by 1/8) ----
        float sA[8][4];
#pragma unroll
        for (int nt = 0; nt < 8; nt++)
#pragma unroll
            for (int i = 0; i < 4; i++) sA[nt][i] = 0.f;
#pragma unroll
        for (int kk = 0; kk < 4; kk++) {
            uint32_t bh[8][2];
#pragma unroll
            for (int nt = 0; nt < 8; nt++) {
                uint32_t rb = buf + (uint32_t)(nt * 8 + rB) * 128
                            + (((uint32_t)(2*kk + uB) * 16) ^ swB);
                ldsm_x2(bh[nt], rb);
            }
#pragma unroll
            for (int nt = 0; nt < 8; nt++) mma16816(sA[nt], qh[kk], bh[nt]);
#pragma unroll
            for (int nt = 0; nt < 8; nt++) mma16816(sA[nt], ql[kk], bh[nt]);
            uint32_t bl[8][2];
#pragma unroll
            for (int nt = 0; nt < 8; nt++) {
                uint32_t rb = buf + 8192 + (uint32_t)(nt * 8 + rB) * 128
                            + (((uint32_t)(2*kk + uB) * 16) ^ swB);
                ldsm_x2(bl[nt], rb);
            }
#pragma unroll
            for (int nt = 0; nt < 8; nt++) mma16816(sA[nt], qh[kk], bl[nt]);
        }

        // ---- causal mask (diagonal tile only; no scale needed) ----
        if (j == qt) {
            const int r0 = qt * 64 + wh * 16 + gid, r1 = r0 + 8;
#pragma unroll
            for (int nt = 0; nt < 8; nt++) {
                int c0 = j * 64 + nt * 8 + 2 * tig;
                if (c0     > r0) sA[nt][0] = -1e30f;
                if (c0 + 1 > r0) sA[nt][1] = -1e30f;
                if (c0     > r1) sA[nt][2] = -1e30f;
                if (c0 + 1 > r1) sA[nt][3] = -1e30f;
            }
        }

        // ---- online softmax ----
        float mx0 = sA[0][0], mx1 = sA[0][2];
#pragma unroll
        for (int nt = 0; nt < 8; nt++) {
            mx0 = fmaxf(mx0, fmaxf(sA[nt][0], sA[nt][1]));
            mx1 = fmaxf(mx1, fmaxf(sA[nt][2], sA[nt][3]));
        }
        mx0 = fmaxf(mx0, __shfl_xor_sync(0xffffffffu, mx0, 1));
        mx0 = fmaxf(mx0, __shfl_xor_sync(0xffffffffu, mx0, 2));
        mx1 = fmaxf(mx1, __shfl_xor_sync(0xffffffffu, mx1, 1));
        mx1 = fmaxf(mx1, __shfl_xor_sync(0xffffffffu, mx1, 2));
        float mn0 = fmaxf(m0r, mx0), mn1 = fmaxf(m1r, mx1);
        float al0 = __expf(m0r - mn0), al1 = __expf(m1r - mn1);
        float ps0 = 0.f, ps1 = 0.f;
#pragma unroll
        for (int nt = 0; nt < 8; nt++) {
            sA[nt][0] = __expf(sA[nt][0] - mn0);
            sA[nt][1] = __expf(sA[nt][1] - mn0);
            sA[nt][2] = __expf(sA[nt][2] - mn1);
            sA[nt][3] = __expf(sA[nt][3] - mn1);
            ps0 += sA[nt][0] + sA[nt][1];
            ps1 += sA[nt][2] + sA[nt][3];
        }
        ps0 += __shfl_xor_sync(0xffffffffu, ps0, 1);
        ps0 += __shfl_xor_sync(0xffffffffu, ps0, 2);
        ps1 += __shfl_xor_sync(0xffffffffu, ps1, 1);
        ps1 += __shfl_xor_sync(0xffffffffu, ps1, 2);
        l0r = l0r * al0 + ps0;  m0r = mn0;
        l1r = l1r * al1 + ps1;  m1r = mn1;
#pragma unroll
        for (int nd = 0; nd < 8; nd++) {
            oA[nd][0] *= al0; oA[nd][1] *= al0;
            oA[nd][2] *= al1; oA[nd][3] *= al1;
        }

        // ---- PV: term-major issue ----
#pragma unroll
        for (int kk = 0; kk < 4; kk++) {
            uint32_t aphi[4], aplo[4];
            {
                __nv_bfloat16 h0,l0,h1,l1;
                split_bf16(sA[2*kk][0], h0, l0);   split_bf16(sA[2*kk][1], h1, l1);
                aphi[0] = pack_bf16x2(h0, h1);     aplo[0] = pack_bf16x2(l0, l1);
                split_bf16(sA[2*kk][2], h0, l0);   split_bf16(sA[2*kk][3], h1, l1);
                aphi[1] = pack_bf16x2(h0, h1);     aplo[1] = pack_bf16x2(l0, l1);
                split_bf16(sA[2*kk+1][0], h0, l0); split_bf16(sA[2*kk+1][1], h1, l1);
                aphi[2] = pack_bf16x2(h0, h1);     aplo[2] = pack_bf16x2(l0, l1);
                split_bf16(sA[2*kk+1][2], h0, l0); split_bf16(sA[2*kk+1][3], h1, l1);
                aphi[3] = pack_bf16x2(h0, h1);     aplo[3] = pack_bf16x2(l0, l1);
            }
            uint32_t vh[8][2];
#pragma unroll
            for (int nd = 0; nd < 8; nd++) {
                uint32_t rv = buf + 16384 + (uint32_t)(nd * 8 + rB) * 128
                            + (((uint32_t)(2*kk + uB) * 16) ^ swB);
                ldsm_x2(vh[nd], rv);
            }
#pragma unroll
            for (int nd = 0; nd < 8; nd++) mma16816(oA[nd], aphi, vh[nd]);
#pragma unroll
            for (int nd = 0; nd < 8; nd++) mma16816(oA[nd], aplo, vh[nd]);
            uint32_t vl[8][2];
#pragma unroll
            for (int nd = 0; nd < 8; nd++) {
                uint32_t rv = buf + 24576 + (uint32_t)(nd * 8 + rB) * 128
                            + (((uint32_t)(2*kk + uB) * 16) ^ swB);
                ldsm_x2(vl[nd], rv);
            }
#pragma unroll
            for (int nd = 0; nd < 8; nd++) mma16816(oA[nd], aphi, vl[nd]);
        }
    }

    const float inv0 = 1.f / l0r, inv1 = 1.f / l1r;
    const size_t out0 = ((size_t)b * TT + qt * 64 + wh * 16 + gid) * DD;
    const size_t out1 = out0 + 8 * DD;
#pragma unroll
    for (int nd = 0; nd < 8; nd++) {
        const int d0 = nd * 8 + 2 * tig;
        *(float2*)&out[out0 + d0] = make_float2(oA[nd][0] * inv0, oA[nd][1] * inv0);
        *(float2*)&out[out1 + d0] = make_float2(oA[nd][2] * inv1, oA[nd][3] * inv1);
    }
}

// ---------------------------------------------------------------------------
extern "C" void kernel_launch(void* const* d_in, const int* in_sizes, int n_in,
                              void* d_out, int out_size)
{
    const float* X  = (const float*)d_in[0];
    const float* Wq = (const float*)d_in[1];
    const float* bq = (const float*)d_in[2];
    const float* Wk = (const float*)d_in[3];
    const float* bk = (const float*)d_in[4];
    const float* Wv = (const float*)d_in[5];
    const float* bv = (const float*)d_in[6];
    float* out = (float*)d_out;

    prep<<<8192 + 16, 256>>>(X, Wq, Wk, Wv);

    cudaFuncSetAttribute(qkv_mma, cudaFuncAttributeMaxDynamicSharedMemorySize, QKV_SMEM);
    qkv_mma<<<MM / 64, 256, QKV_SMEM>>>(bq, bk, bv);

    cudaFuncSetAttribute(attn_mma, cudaFuncAttributeMaxDynamicSharedMemorySize, ATTN_SMEM);
    attn_mma<<<dim3(32, BB), 256, ATTN_SMEM>>>(out);
}

// round 9
// speedup vs baseline: 1.2874x; 1.1367x over previous
#include <cuda_runtime.h>
#include <cuda_bf16.h>
#include <cuda_fp16.h>
#include <cstdint>
#include <math.h>

#define BB 4
#define TT 4096
#define EE 1024
#define DD 64
#define MM (BB*TT)

// ---------------------------------------------------------------------------
// Device scratch.  Q: fp16 hi/lo. K: single fp16. V: single fp16, transposed.
// ---------------------------------------------------------------------------
__device__ __half g_qhi[MM*DD];
__device__ __half g_qlo[MM*DD];
__device__ __half g_kh [MM*DD];
__device__ __half g_vth[MM*DD];

#define WCHUNK_BYTES (192*128)
__device__ unsigned char g_whi[16*WCHUNK_BYTES];
__device__ unsigned char g_wlo[16*WCHUNK_BYTES];

__device__ unsigned char g_xhi[(size_t)MM*16*128];
__device__ unsigned char g_xlo[(size_t)MM*16*128];

// ---------------------------------------------------------------------------
// Helpers
// ---------------------------------------------------------------------------
#define DEVINL __device__ __forceinline__

DEVINL uint32_t smem_u32(const void* p) {
    uint32_t a;
    asm("{ .reg .u64 t; cvta.to.shared.u64 t, %1; cvt.u32.u64 %0, t; }"
        : "=r"(a) : "l"(p));
    return a;
}

#define SWZ128(o) ((o) ^ (((o) >> 3) & 0x70))

#define CP_ASYNC16(dst, src) \
    asm volatile("cp.async.cg.shared.global [%0], [%1], 16;" \
                 :: "r"(dst), "l"(src) : "memory")
#define CP_COMMIT() asm volatile("cp.async.commit_group;" ::: "memory")
#define CP_WAIT0()  asm volatile("cp.async.wait_group 0;"  ::: "memory")

#define NB_SYNC(id) asm volatile("bar.sync %0, 128;" :: "r"(id) : "memory")

DEVINL uint32_t pack_bf16x2(__nv_bfloat16 a, __nv_bfloat16 b) {
    return (uint32_t)__bfloat16_as_ushort(a) |
           ((uint32_t)__bfloat16_as_ushort(b) << 16);
}
DEVINL void split_bf16(float x, __nv_bfloat16& h, __nv_bfloat16& l) {
    h = __float2bfloat16(x);
    l = __float2bfloat16(x - __bfloat162float(h));
}
DEVINL uint32_t pack_h2(__half a, __half b) {
    return (uint32_t)__half_as_ushort(a) |
           ((uint32_t)__half_as_ushort(b) << 16);
}
DEVINL void split_f16(float x, __half& h, __half& l) {
    h = __float2half_rn(x);
    l = __float2half_rn(x - __half2float(h));
}

DEVINL void ldsm_x4(uint32_t r[4], uint32_t addr) {
    asm volatile("ldmatrix.sync.aligned.m8n8.x4.shared.b16 {%0,%1,%2,%3}, [%4];"
        : "=r"(r[0]), "=r"(r[1]), "=r"(r[2]), "=r"(r[3]) : "r"(addr));
}
DEVINL void ldsm_x2(uint32_t r[2], uint32_t addr) {
    asm volatile("ldmatrix.sync.aligned.m8n8.x2.shared.b16 {%0,%1}, [%2];"
        : "=r"(r[0]), "=r"(r[1]) : "r"(addr));
}
// bf16 MMA (qkv path)
DEVINL void mma16816(float c[4], const uint32_t a[4], const uint32_t b[2]) {
    asm volatile(
        "mma.sync.aligned.m16n8k16.row.col.f32.bf16.bf16.f32 "
        "{%0,%1,%2,%3}, {%4,%5,%6,%7}, {%8,%9}, {%0,%1,%2,%3};"
        : "+f"(c[0]), "+f"(c[1]), "+f"(c[2]), "+f"(c[3])
        : "r"(a[0]), "r"(a[1]), "r"(a[2]), "r"(a[3]), "r"(b[0]), "r"(b[1]));
}
// fp16 MMA (attention path)
DEVINL void mma16816h(float c[4], const uint32_t a[4], const uint32_t b[2]) {
    asm volatile(
        "mma.sync.aligned.m16n8k16.row.col.f32.f16.f16.f32 "
        "{%0,%1,%2,%3}, {%4,%5,%6,%7}, {%8,%9}, {%0,%1,%2,%3};"
        : "+f"(c[0]), "+f"(c[1]), "+f"(c[2]), "+f"(c[3])
        : "r"(a[0]), "r"(a[1]), "r"(a[2]), "r"(a[3]), "r"(b[0]), "r"(b[1]));
}

// ---------------------------------------------------------------------------
// Merged prep (unchanged): blocks < 8192 split X; rest split/transpose W.
// ---------------------------------------------------------------------------
__global__ __launch_bounds__(256) void prep(
    const float* __restrict__ X,
    const float* __restrict__ Wq, const float* __restrict__ Wk,
    const float* __restrict__ Wv)
{
    if (blockIdx.x < 8192) {
        const int u = blockIdx.x * 256 + threadIdx.x;
        const int row  = u >> 7;
        const int unit = u & 127;
        const int c    = unit >> 3;
        const int col8 = unit & 7;
        const float4 a = *(const float4*)&X[(size_t)row * EE + c * 64 + col8 * 8];
        const float4 b = *(const float4*)&X[(size_t)row * EE + c * 64 + col8 * 8 + 4];
        __nv_bfloat16 h0,l0,h1,l1,h2,l2,h3,l3,h4,l4,h5,l5,h6,l6,h7,l7;
        split_bf16(a.x, h0, l0); split_bf16(a.y, h1, l1);
        split_bf16(a.z, h2, l2); split_bf16(a.w, h3, l3);
        split_bf16(b.x, h4, l4); split_bf16(b.y, h5, l5);
        split_bf16(b.z, h6, l6); split_bf16(b.w, h7, l7);
        uint4 hh = make_uint4(pack_bf16x2(h0,h1), pack_bf16x2(h2,h3),
                              pack_bf16x2(h4,h5), pack_bf16x2(h6,h7));
        uint4 ll = make_uint4(pack_bf16x2(l0,l1), pack_bf16x2(l2,l3),
                              pack_bf16x2(l4,l5), pack_bf16x2(l6,l7));
        size_t off = (((size_t)row * 16 + c) << 7)
                   + ((((uint32_t)col8 * 16) ^ ((uint32_t)(row & 7) << 4)));
        *(uint4*)(g_xhi + off) = hh;
        *(uint4*)(g_xlo + off) = ll;
    } else {
        const int c = blockIdx.x - 8192;
        for (int it = threadIdx.x; it < 1536; it += 256) {
            int n = it % 192;
            int g = it / 192;
            int mat = n >> 6, d = n & 63;
            const float* Wm = (mat == 0) ? Wq : (mat == 1) ? Wk : Wv;
            int kk0 = g * 8;
            uint32_t hi[4], lo[4];
#pragma unroll
            for (int j = 0; j < 4; j++) {
                __nv_bfloat16 h0, l0, h1, l1;
                split_bf16(Wm[(size_t)(c*64 + kk0 + 2*j    ) * 64 + d], h0, l0);
                split_bf16(Wm[(size_t)(c*64 + kk0 + 2*j + 1) * 64 + d], h1, l1);
                hi[j] = pack_bf16x2(h0, h1);
                lo[j] = pack_bf16x2(l0, l1);
            }
            uint32_t sw = SWZ128((uint32_t)n * 128 + (uint32_t)kk0 * 2);
            *(uint4*)(g_whi + (size_t)c * WCHUNK_BYTES + sw) = make_uint4(hi[0], hi[1], hi[2], hi[3]);
            *(uint4*)(g_wlo + (size_t)c * WCHUNK_BYTES + sw) = make_uint4(lo[0], lo[1], lo[2], lo[3]);
        }
    }
}

// ---------------------------------------------------------------------------
// QKV via mma.sync bf16 3-term (fp32-grade). Epilogue: q scaled by 1/8 and
// split to fp16 hi/lo; k, v rounded to single fp16 (v transposed).
// ---------------------------------------------------------------------------
#define QB_A_HI 0
#define QB_A_LO 8192
#define QB_B_HI 16384
#define QB_B_LO 40960
#define QB_STRIDE 65536
#define QKV_SMEM (2*QB_STRIDE)

__global__ __launch_bounds__(256, 1) void qkv_mma(
    const float* __restrict__ bq, const float* __restrict__ bk,
    const float* __restrict__ bv)
{
    extern __shared__ __align__(1024) unsigned char sm[];
    const uint32_t sb = smem_u32(sm);
    const int tid  = threadIdx.x;
    const int warp = tid >> 5;
    const int lane = tid & 31;
    const int m0   = blockIdx.x * 64;
    const int wbase = warp * 24;

    const int rA = (lane & 7) | (((lane >> 3) & 1) << 3);
    const int uA = lane >> 4;
    const int rB = lane & 7;
    const int uB = (lane >> 3) & 1;
    const uint32_t swA = (uint32_t)(rA & 7) << 4;
    const uint32_t swB = (uint32_t)(rB & 7) << 4;

    float acc[4][3][4];
#pragma unroll
    for (int mt = 0; mt < 4; mt++)
#pragma unroll
        for (int nt = 0; nt < 3; nt++)
#pragma unroll
            for (int i = 0; i < 4; i++) acc[mt][nt][i] = 0.f;

    {
#pragma unroll
        for (int j = 0; j < 6; j++) {
            int f = tid + 256 * j;
            CP_ASYNC16(sb + QB_B_HI + f * 16, g_whi + (size_t)f * 16);
            CP_ASYNC16(sb + QB_B_LO + f * 16, g_wlo + (size_t)f * 16);
        }
#pragma unroll
        for (int i = 0; i < 4; i++) {
            int u = tid + 256 * i;
            int mat = u >> 9, w = u & 511;
            size_t src = (((size_t)(m0 + (w >> 3)) * 16) << 7) + (w & 7) * 16;
            const unsigned char* sp = (mat ? g_xlo : g_xhi) + src;
            CP_ASYNC16(sb + (mat ? QB_A_LO : QB_A_HI) + (uint32_t)w * 16, sp);
        }
        CP_COMMIT();
        CP_WAIT0();
        __syncthreads();
    }

    for (int c = 0; c < 16; c++) {
        const uint32_t bufc = sb + (uint32_t)(c & 1) * QB_STRIDE;
        const uint32_t bufn = sb + (uint32_t)((c + 1) & 1) * QB_STRIDE;
        const bool hasNext = (c < 15);

        if (hasNext) {
            const unsigned char* wh = g_whi + (size_t)(c + 1) * WCHUNK_BYTES;
            const unsigned char* wl = g_wlo + (size_t)(c + 1) * WCHUNK_BYTES;
#pragma unroll
            for (int j = 0; j < 6; j++) {
                int f = tid + 256 * j;
                CP_ASYNC16(bufn + QB_B_HI + f * 16, wh + (size_t)f * 16);
                CP_ASYNC16(bufn + QB_B_LO + f * 16, wl + (size_t)f * 16);
            }
#pragma unroll
            for (int i = 0; i < 4; i++) {
                int u = tid + 256 * i;
                int mat = u >> 9, w = u & 511;
                size_t src = (((size_t)(m0 + (w >> 3)) * 16 + (c + 1)) << 7) + (w & 7) * 16;
                const unsigned char* sp = (mat ? g_xlo : g_xhi) + src;
                CP_ASYNC16(bufn + (mat ? QB_A_LO : QB_A_HI) + (uint32_t)w * 16, sp);
            }
            CP_COMMIT();
        }

#pragma unroll
        for (int kk = 0; kk < 4; kk++) {
            uint32_t ah[4][4], al[4][4];
#pragma unroll
            for (int mt = 0; mt < 4; mt++) {
                uint32_t ra = bufc + QB_A_HI + (uint32_t)(16*mt + rA) * 128
                            + (((uint32_t)(2*kk + uA) * 16) ^ swA);
                ldsm_x4(ah[mt], ra);
                ldsm_x4(al[mt], ra + (QB_A_LO - QB_A_HI));
            }
            uint32_t bh[3][2], bl[3][2];
#pragma unroll
            for (int nt = 0; nt < 3; nt++) {
                uint32_t rb = bufc + QB_B_HI + (uint32_t)(wbase + 8*nt + rB) * 128
                            + (((uint32_t)(2*kk + uB) * 16) ^ swB);
                ldsm_x2(bh[nt], rb);
                ldsm_x2(bl[nt], rb + (QB_B_LO - QB_B_HI));
            }
#pragma unroll
            for (int mt = 0; mt < 4; mt++)
#pragma unroll
                for (int nt = 0; nt < 3; nt++)
                    mma16816(acc[mt][nt], ah[mt], bh[nt]);
#pragma unroll
            for (int mt = 0; mt < 4; mt++)
#pragma unroll
                for (int nt = 0; nt < 3; nt++)
                    mma16816(acc[mt][nt], ah[mt], bl[nt]);
#pragma unroll
            for (int mt = 0; mt < 4; mt++)
#pragma unroll
                for (int nt = 0; nt < 3; nt++)
                    mma16816(acc[mt][nt], al[mt], bh[nt]);
        }

        CP_WAIT0();
        __syncthreads();
    }

    const int gid = lane >> 2, tig = lane & 3;
#pragma unroll
    for (int mt = 0; mt < 4; mt++) {
#pragma unroll
        for (int nt = 0; nt < 3; nt++) {
            const int col0 = wbase + 8 * nt;
            const int mat  = col0 >> 6;
            const int d0   = (col0 & 63) + 2 * tig;
            const float* bp = (mat == 0) ? bq : (mat == 1) ? bk : bv;
            const float b0v = bp[d0], b1v = bp[d0 + 1];
            const int row0 = m0 + 16 * mt + gid;
            float v00 = acc[mt][nt][0] + b0v, v01 = acc[mt][nt][1] + b1v;
            float v10 = acc[mt][nt][2] + b0v, v11 = acc[mt][nt][3] + b1v;
            if (mat == 0) {
                // fold score scale into q (exact *2^-3), split to fp16 hi/lo
                v00 *= 0.125f; v01 *= 0.125f; v10 *= 0.125f; v11 *= 0.125f;
                __half h00,l00,h01,l01,h10,l10,h11,l11;
                split_f16(v00, h00, l00); split_f16(v01, h01, l01);
                split_f16(v10, h10, l10); split_f16(v11, h11, l11);
                *(uint32_t*)&g_qhi[(size_t)row0 * DD + d0]       = pack_h2(h00, h01);
                *(uint32_t*)&g_qlo[(size_t)row0 * DD + d0]       = pack_h2(l00, l01);
                *(uint32_t*)&g_qhi[(size_t)(row0 + 8) * DD + d0] = pack_h2(h10, h11);
                *(uint32_t*)&g_qlo[(size_t)(row0 + 8) * DD + d0] = pack_h2(l10, l11);
            } else if (mat == 1) {
                *(uint32_t*)&g_kh[(size_t)row0 * DD + d0] =
                    pack_h2(__float2half_rn(v00), __float2half_rn(v01));
                *(uint32_t*)&g_kh[(size_t)(row0 + 8) * DD + d0] =
                    pack_h2(__float2half_rn(v10), __float2half_rn(v11));
            } else {
                const int bb = row0 >> 12, t = row0 & 4095;
                size_t r0o = ((size_t)bb * 64 + d0) * TT + t;
                size_t r1o = ((size_t)bb * 64 + d0 + 1) * TT + t;
                g_vth[r0o]     = __float2half_rn(v00);
                g_vth[r1o]     = __float2half_rn(v01);
                g_vth[r0o + 8] = __float2half_rn(v10);
                g_vth[r1o + 8] = __float2half_rn(v11);
            }
        }
    }
}

// ---------------------------------------------------------------------------
// Flash attention, fp16 2-term: S = (qh+ql)·kh, O += (Phi+Plo)·vh.
// Paired halves, double-buffered KV (single-word K and V).
// Per half: Qhi 8K @0, Qlo 8K @8192, K stages @16384 (2x8K), V @32768 (2x8K).
// ---------------------------------------------------------------------------
#define AH_STRIDE 49152
#define ATTN_SMEM (2*AH_STRIDE)   // 98304

DEVINL void stage_kv(uint32_t kdst, uint32_t vdst, int htid, int b, int t0) {
#pragma unroll
    for (int i = 0; i < 8; i++) {
        int u = htid + 128 * i;                // 0..1023
        int mat = u >> 9, w = u & 511, r = w >> 3, cu = w & 7;
        const __half* src = mat
            ? g_vth + ((size_t)b * DD + r) * TT + t0 + cu * 8
            : g_kh  + (size_t)(b * TT + t0 + r) * DD + cu * 8;
        uint32_t dst = (mat ? vdst : kdst) + (uint32_t)r * 128
                     + (((uint32_t)cu * 16) ^ ((uint32_t)(r & 7) << 4));
        CP_ASYNC16(dst, src);
    }
}

__global__ __launch_bounds__(256, 1) void attn_mma(float* __restrict__ out)
{
    extern __shared__ __align__(1024) unsigned char sm[];
    const uint32_t sb = smem_u32(sm);
    const int tid  = threadIdx.x;
    const int warp = tid >> 5;
    const int lane = tid & 31;
    const int half = warp >> 2;
    const int wh   = warp & 3;
    const int htid = tid & 127;
    const int b    = blockIdx.y;
    const int qp   = blockIdx.x;
    const int qt   = half ? (63 - qp) : qp;
    const uint32_t hb = sb + (uint32_t)half * AH_STRIDE;
    const int tok0 = b * TT + qt * 64;
    const int nbid = half + 1;

    const int gid = lane >> 2, tig = lane & 3;
    const int rA = (lane & 7) | (((lane >> 3) & 1) << 3);
    const int uA = lane >> 4;
    const int rB = lane & 7;
    const int uB = (lane >> 3) & 1;
    const uint32_t swA = (uint32_t)(rA & 7) << 4;
    const uint32_t swB = (uint32_t)(rB) << 4;

    // ---- stage Q (hi/lo) + KV tile 0 ----
#pragma unroll
    for (int i = 0; i < 8; i++) {
        int u = htid + 128 * i;                // 0..1023
        int matq = u >> 9, r = (u >> 3) & 63, cu = u & 7;
        const __half* src = (matq ? g_qlo : g_qhi)
                          + (size_t)(tok0 + r) * DD + cu * 8;
        uint32_t dst = hb + matq * 8192 + (uint32_t)r * 128
                     + (((uint32_t)cu * 16) ^ ((uint32_t)(r & 7) << 4));
        CP_ASYNC16(dst, src);
    }
    stage_kv(hb + 16384, hb + 32768, htid, b, 0);
    CP_COMMIT();
    CP_WAIT0();
    NB_SYNC(nbid);

    uint32_t qh[4][4], ql[4][4];
#pragma unroll
    for (int kk = 0; kk < 4; kk++) {
        uint32_t ra = hb + (uint32_t)(wh * 16 + rA) * 128
                    + (((uint32_t)(2*kk + uA) * 16) ^ swA);
        ldsm_x4(qh[kk], ra);
        ldsm_x4(ql[kk], ra + 8192);
    }

    float oA[8][4];
#pragma unroll
    for (int nd = 0; nd < 8; nd++)
#pragma unroll
        for (int i = 0; i < 4; i++) oA[nd][i] = 0.f;
    float m0r = -3.0e38f, m1r = -3.0e38f, l0r = 0.f, l1r = 0.f;

    for (int j = 0; j <= qt; j++) {
        if (j) { CP_WAIT0(); NB_SYNC(nbid); }
        const uint32_t kbase = hb + 16384 + (uint32_t)(j & 1) * 8192;
        const uint32_t vbase = hb + 32768 + (uint32_t)(j & 1) * 8192;

        if (j < qt) {
            stage_kv(hb + 16384 + (uint32_t)((j + 1) & 1) * 8192,
                     hb + 32768 + (uint32_t)((j + 1) & 1) * 8192,
                     htid, b, (j + 1) * 64);
            CP_COMMIT();
        }

        // ---- S = Q . K^T  (2 fp16 MMAs per accumulator per kk) ----
        float sA[8][4];
#pragma unroll
        for (int nt = 0; nt < 8; nt++)
#pragma unroll
            for (int i = 0; i < 4; i++) sA[nt][i] = 0.f;
#pragma unroll
        for (int kk = 0; kk < 4; kk++) {
            uint32_t bh[8][2];
#pragma unroll
            for (int nt = 0; nt < 8; nt++) {
                uint32_t rb = kbase + (uint32_t)(nt * 8 + rB) * 128
                            + (((uint32_t)(2*kk + uB) * 16) ^ swB);
                ldsm_x2(bh[nt], rb);
            }
#pragma unroll
            for (int nt = 0; nt < 8; nt++) mma16816h(sA[nt], qh[kk], bh[nt]);
#pragma unroll
            for (int nt = 0; nt < 8; nt++) mma16816h(sA[nt], ql[kk], bh[nt]);
        }

        // ---- causal mask (diagonal tile only; scale folded into q) ----
        if (j == qt) {
            const int r0 = qt * 64 + wh * 16 + gid, r1 = r0 + 8;
#pragma unroll
            for (int nt = 0; nt < 8; nt++) {
                int c0 = j * 64 + nt * 8 + 2 * tig;
                if (c0     > r0) sA[nt][0] = -1e30f;
                if (c0 + 1 > r0) sA[nt][1] = -1e30f;
                if (c0     > r1) sA[nt][2] = -1e30f;
                if (c0 + 1 > r1) sA[nt][3] = -1e30f;
            }
        }

        // ---- online softmax ----
        float mx0 = sA[0][0], mx1 = sA[0][2];
#pragma unroll
        for (int nt = 0; nt < 8; nt++) {
            mx0 = fmaxf(mx0, fmaxf(sA[nt][0], sA[nt][1]));
            mx1 = fmaxf(mx1, fmaxf(sA[nt][2], sA[nt][3]));
        }
        mx0 = fmaxf(mx0, __shfl_xor_sync(0xffffffffu, mx0, 1));
        mx0 = fmaxf(mx0, __shfl_xor_sync(0xffffffffu, mx0, 2));
        mx1 = fmaxf(mx1, __shfl_xor_sync(0xffffffffu, mx1, 1));
        mx1 = fmaxf(mx1, __shfl_xor_sync(0xffffffffu, mx1, 2));
        float mn0 = fmaxf(m0r, mx0), mn1 = fmaxf(m1r, mx1);
        float al0 = __expf(m0r - mn0), al1 = __expf(m1r - mn1);
        float ps0 = 0.f, ps1 = 0.f;
#pragma unroll
        for (int nt = 0; nt < 8; nt++) {
            sA[nt][0] = __expf(sA[nt][0] - mn0);
            sA[nt][1] = __expf(sA[nt][1] - mn0);
            sA[nt][2] = __expf(sA[nt][2] - mn1);
            sA[nt][3] = __expf(sA[nt][3] - mn1);
            ps0 += sA[nt][0] + sA[nt][1];
            ps1 += sA[nt][2] + sA[nt][3];
        }
        ps0 += __shfl_xor_sync(0xffffffffu, ps0, 1);
        ps0 += __shfl_xor_sync(0xffffffffu, ps0, 2);
        ps1 += __shfl_xor_sync(0xffffffffu, ps1, 1);
        ps1 += __shfl_xor_sync(0xffffffffu, ps1, 2);
        l0r = l0r * al0 + ps0;  m0r = mn0;
        l1r = l1r * al1 + ps1;  m1r = mn1;
#pragma unroll
        for (int nd = 0; nd < 8; nd++) {
            oA[nd][0] *= al0; oA[nd][1] *= al0;
            oA[nd][2] *= al1; oA[nd][3] *= al1;
        }

        // ---- PV: O += (Phi + Plo) . Vh  (2 fp16 MMAs per acc per kk) ----
#pragma unroll
        for (int kk = 0; kk < 4; kk++) {
            uint32_t aphi[4], aplo[4];
            {
                __half h0,l0,h1,l1;
                split_f16(sA[2*kk][0], h0, l0);   split_f16(sA[2*kk][1], h1, l1);
                aphi[0] = pack_h2(h0, h1);        aplo[0] = pack_h2(l0, l1);
                split_f16(sA[2*kk][2], h0, l0);   split_f16(sA[2*kk][3], h1, l1);
                aphi[1] = pack_h2(h0, h1);        aplo[1] = pack_h2(l0, l1);
                split_f16(sA[2*kk+1][0], h0, l0); split_f16(sA[2*kk+1][1], h1, l1);
                aphi[2] = pack_h2(h0, h1);        aplo[2] = pack_h2(l0, l1);
                split_f16(sA[2*kk+1][2], h0, l0); split_f16(sA[2*kk+1][3], h1, l1);
                aphi[3] = pack_h2(h0, h1);        aplo[3] = pack_h2(l0, l1);
            }
            uint32_t vh[8][2];
#pragma unroll
            for (int nd = 0; nd < 8; nd++) {
                uint32_t rv = vbase + (uint32_t)(nd * 8 + rB) * 128
                            + (((uint32_t)(2*kk + uB) * 16) ^ swB);
                ldsm_x2(vh[nd], rv);
            }
#pragma unroll
            for (int nd = 0; nd < 8; nd++) mma16816h(oA[nd], aphi, vh[nd]);
#pragma unroll
            for (int nd = 0; nd < 8; nd++) mma16816h(oA[nd], aplo, vh[nd]);
        }
    }

    const float inv0 = 1.f / l0r, inv1 = 1.f / l1r;
    const size_t out0 = ((size_t)b * TT + qt * 64 + wh * 16 + gid) * DD;
    const size_t out1 = out0 + 8 * DD;
#pragma unroll
    for (int nd = 0; nd < 8; nd++) {
        const int d0 = nd * 8 + 2 * tig;
        *(float2*)&out[out0 + d0] = make_float2(oA[nd][0] * inv0, oA[nd][1] * inv0);
        *(float2*)&out[out1 + d0] = make_float2(oA[nd][2] * inv1, oA[nd][3] * inv1);
    }
}

// ---------------------------------------------------------------------------
extern "C" void kernel_launch(void* const* d_in, const int* in_sizes, int n_in,
                              void* d_out, int out_size)
{
    const float* X  = (const float*)d_in[0];
    const float* Wq = (const float*)d_in[1];
    const float* bq = (const float*)d_in[2];
    const float* Wk = (const float*)d_in[3];
    const float* bk = (const float*)d_in[4];
    const float* Wv = (const float*)d_in[5];
    const float* bv = (const float*)d_in[6];
    float* out = (float*)d_out;

    prep<<<8192 + 16, 256>>>(X, Wq, Wk, Wv);

    cudaFuncSetAttribute(qkv_mma, cudaFuncAttributeMaxDynamicSharedMemorySize, QKV_SMEM);
    qkv_mma<<<MM / 64, 256, QKV_SMEM>>>(bq, bk, bv);

    cudaFuncSetAttribute(attn_mma, cudaFuncAttributeMaxDynamicSharedMemorySize, ATTN_SMEM);
    attn_mma<<<dim3(32, BB), 256, ATTN_SMEM>>>(out);
}

// round 10
// speedup vs baseline: 1.4237x; 1.1058x over previous
#include <cuda_runtime.h>
#include <cuda_bf16.h>
#include <cuda_fp16.h>
#include <cstdint>
#include <math.h>

#define BB 4
#define TT 4096
#define EE 1024
#define DD 64
#define MM (BB*TT)

// ---------------------------------------------------------------------------
// Device scratch.  Q: fp16 hi/lo. K: single fp16. V: single fp16, transposed.
// ---------------------------------------------------------------------------
__device__ __half g_qhi[MM*DD];
__device__ __half g_qlo[MM*DD];
__device__ __half g_kh [MM*DD];
__device__ __half g_vth[MM*DD];

// W: single fp16, transposed (rows n = mat*64+d, 64 k per row), SW128/chunk
#define WCHUNK_BYTES (192*128)
__device__ unsigned char g_wh[16*WCHUNK_BYTES];

// X: fp16 hi/lo, pre-swizzled [row][16 k-chunks][128 bytes]
__device__ unsigned char g_xhi[(size_t)MM*16*128];
__device__ unsigned char g_xlo[(size_t)MM*16*128];

// ---------------------------------------------------------------------------
// Helpers
// ---------------------------------------------------------------------------
#define DEVINL __device__ __forceinline__

DEVINL uint32_t smem_u32(const void* p) {
    uint32_t a;
    asm("{ .reg .u64 t; cvta.to.shared.u64 t, %1; cvt.u32.u64 %0, t; }"
        : "=r"(a) : "l"(p));
    return a;
}

#define SWZ128(o) ((o) ^ (((o) >> 3) & 0x70))

#define CP_ASYNC16(dst, src) \
    asm volatile("cp.async.cg.shared.global [%0], [%1], 16;" \
                 :: "r"(dst), "l"(src) : "memory")
#define CP_COMMIT() asm volatile("cp.async.commit_group;" ::: "memory")
#define CP_WAIT0()  asm volatile("cp.async.wait_group 0;"  ::: "memory")

#define NB_SYNC(id) asm volatile("bar.sync %0, 128;" :: "r"(id) : "memory")

DEVINL uint32_t pack_h2(__half a, __half b) {
    return (uint32_t)__half_as_ushort(a) |
           ((uint32_t)__half_as_ushort(b) << 16);
}
DEVINL void split_f16(float x, __half& h, __half& l) {
    h = __float2half_rn(x);
    l = __float2half_rn(x - __half2float(h));
}

DEVINL void ldsm_x4(uint32_t r[4], uint32_t addr) {
    asm volatile("ldmatrix.sync.aligned.m8n8.x4.shared.b16 {%0,%1,%2,%3}, [%4];"
        : "=r"(r[0]), "=r"(r[1]), "=r"(r[2]), "=r"(r[3]) : "r"(addr));
}
DEVINL void ldsm_x2(uint32_t r[2], uint32_t addr) {
    asm volatile("ldmatrix.sync.aligned.m8n8.x2.shared.b16 {%0,%1}, [%2];"
        : "=r"(r[0]), "=r"(r[1]) : "r"(addr));
}
DEVINL void mma16816h(float c[4], const uint32_t a[4], const uint32_t b[2]) {
    asm volatile(
        "mma.sync.aligned.m16n8k16.row.col.f32.f16.f16.f32 "
        "{%0,%1,%2,%3}, {%4,%5,%6,%7}, {%8,%9}, {%0,%1,%2,%3};"
        : "+f"(c[0]), "+f"(c[1]), "+f"(c[2]), "+f"(c[3])
        : "r"(a[0]), "r"(a[1]), "r"(a[2]), "r"(a[3]), "r"(b[0]), "r"(b[1]));
}

// ---------------------------------------------------------------------------
// Merged prep: blocks < 8192 split X (fp16 hi/lo); rest W (single fp16).
// ---------------------------------------------------------------------------
__global__ __launch_bounds__(256) void prep(
    const float* __restrict__ X,
    const float* __restrict__ Wq, const float* __restrict__ Wk,
    const float* __restrict__ Wv)
{
    if (blockIdx.x < 8192) {
        const int u = blockIdx.x * 256 + threadIdx.x;
        const int row  = u >> 7;
        const int unit = u & 127;
        const int c    = unit >> 3;
        const int col8 = unit & 7;
        const float4 a = *(const float4*)&X[(size_t)row * EE + c * 64 + col8 * 8];
        const float4 b = *(const float4*)&X[(size_t)row * EE + c * 64 + col8 * 8 + 4];
        __half h0,l0,h1,l1,h2,l2,h3,l3,h4,l4,h5,l5,h6,l6,h7,l7;
        split_f16(a.x, h0, l0); split_f16(a.y, h1, l1);
        split_f16(a.z, h2, l2); split_f16(a.w, h3, l3);
        split_f16(b.x, h4, l4); split_f16(b.y, h5, l5);
        split_f16(b.z, h6, l6); split_f16(b.w, h7, l7);
        uint4 hh = make_uint4(pack_h2(h0,h1), pack_h2(h2,h3),
                              pack_h2(h4,h5), pack_h2(h6,h7));
        uint4 ll = make_uint4(pack_h2(l0,l1), pack_h2(l2,l3),
                              pack_h2(l4,l5), pack_h2(l6,l7));
        size_t off = (((size_t)row * 16 + c) << 7)
                   + ((((uint32_t)col8 * 16) ^ ((uint32_t)(row & 7) << 4)));
        *(uint4*)(g_xhi + off) = hh;
        *(uint4*)(g_xlo + off) = ll;
    } else {
        const int c = blockIdx.x - 8192;
        for (int it = threadIdx.x; it < 1536; it += 256) {
            int n = it % 192;
            int g = it / 192;
            int mat = n >> 6, d = n & 63;
            const float* Wm = (mat == 0) ? Wq : (mat == 1) ? Wk : Wv;
            int kk0 = g * 8;
            uint32_t hi[4];
#pragma unroll
            for (int j = 0; j < 4; j++) {
                __half h0 = __float2half_rn(Wm[(size_t)(c*64 + kk0 + 2*j    ) * 64 + d]);
                __half h1 = __float2half_rn(Wm[(size_t)(c*64 + kk0 + 2*j + 1) * 64 + d]);
                hi[j] = pack_h2(h0, h1);
            }
            uint32_t sw = SWZ128((uint32_t)n * 128 + (uint32_t)kk0 * 2);
            *(uint4*)(g_wh + (size_t)c * WCHUNK_BYTES + sw) = make_uint4(hi[0], hi[1], hi[2], hi[3]);
        }
    }
}

// ---------------------------------------------------------------------------
// QKV via mma.sync, fp16 one-sided split: acc += (Xhi + Xlo) . Wh.
// CTA tile M=64, N=192, k-chunks of 64, double-buffered.
// Buffer: A hi 8K @0, A lo 8K @8192, B 24K @16384. Stride 40960.
// ---------------------------------------------------------------------------
#define QB_A_HI 0
#define QB_A_LO 8192
#define QB_B    16384
#define QB_STRIDE 40960
#define QKV_SMEM (2*QB_STRIDE)   // 81920

__global__ __launch_bounds__(256, 1) void qkv_mma(
    const float* __restrict__ bq, const float* __restrict__ bk,
    const float* __restrict__ bv)
{
    extern __shared__ __align__(1024) unsigned char sm[];
    const uint32_t sb = smem_u32(sm);
    const int tid  = threadIdx.x;
    const int warp = tid >> 5;
    const int lane = tid & 31;
    const int m0   = blockIdx.x * 64;
    const int wbase = warp * 24;

    const int rA = (lane & 7) | (((lane >> 3) & 1) << 3);
    const int uA = lane >> 4;
    const int rB = lane & 7;
    const int uB = (lane >> 3) & 1;
    const uint32_t swA = (uint32_t)(rA & 7) << 4;
    const uint32_t swB = (uint32_t)(rB & 7) << 4;

    float acc[4][3][4];
#pragma unroll
    for (int mt = 0; mt < 4; mt++)
#pragma unroll
        for (int nt = 0; nt < 3; nt++)
#pragma unroll
            for (int i = 0; i < 4; i++) acc[mt][nt][i] = 0.f;

    {
#pragma unroll
        for (int j = 0; j < 6; j++) {
            int f = tid + 256 * j;
            CP_ASYNC16(sb + QB_B + f * 16, g_wh + (size_t)f * 16);
        }
#pragma unroll
        for (int i = 0; i < 4; i++) {
            int u = tid + 256 * i;
            int mat = u >> 9, w = u & 511;
            size_t src = (((size_t)(m0 + (w >> 3)) * 16) << 7) + (w & 7) * 16;
            const unsigned char* sp = (mat ? g_xlo : g_xhi) + src;
            CP_ASYNC16(sb + (mat ? QB_A_LO : QB_A_HI) + (uint32_t)w * 16, sp);
        }
        CP_COMMIT();
        CP_WAIT0();
        __syncthreads();
    }

    for (int c = 0; c < 16; c++) {
        const uint32_t bufc = sb + (uint32_t)(c & 1) * QB_STRIDE;
        const uint32_t bufn = sb + (uint32_t)((c + 1) & 1) * QB_STRIDE;
        const bool hasNext = (c < 15);

        if (hasNext) {
            const unsigned char* wh = g_wh + (size_t)(c + 1) * WCHUNK_BYTES;
#pragma unroll
            for (int j = 0; j < 6; j++) {
                int f = tid + 256 * j;
                CP_ASYNC16(bufn + QB_B + f * 16, wh + (size_t)f * 16);
            }
#pragma unroll
            for (int i = 0; i < 4; i++) {
                int u = tid + 256 * i;
                int mat = u >> 9, w = u & 511;
                size_t src = (((size_t)(m0 + (w >> 3)) * 16 + (c + 1)) << 7) + (w & 7) * 16;
                const unsigned char* sp = (mat ? g_xlo : g_xhi) + src;
                CP_ASYNC16(bufn + (mat ? QB_A_LO : QB_A_HI) + (uint32_t)w * 16, sp);
            }
            CP_COMMIT();
        }

#pragma unroll
        for (int kk = 0; kk < 4; kk++) {
            uint32_t ah[4][4], al[4][4];
#pragma unroll
            for (int mt = 0; mt < 4; mt++) {
                uint32_t ra = bufc + QB_A_HI + (uint32_t)(16*mt + rA) * 128
                            + (((uint32_t)(2*kk + uA) * 16) ^ swA);
                ldsm_x4(ah[mt], ra);
                ldsm_x4(al[mt], ra + (QB_A_LO - QB_A_HI));
            }
            uint32_t bh[3][2];
#pragma unroll
            for (int nt = 0; nt < 3; nt++) {
                uint32_t rb = bufc + QB_B + (uint32_t)(wbase + 8*nt + rB) * 128
                            + (((uint32_t)(2*kk + uB) * 16) ^ swB);
                ldsm_x2(bh[nt], rb);
            }
#pragma unroll
            for (int mt = 0; mt < 4; mt++)
#pragma unroll
                for (int nt = 0; nt < 3; nt++)
                    mma16816h(acc[mt][nt], ah[mt], bh[nt]);
#pragma unroll
            for (int mt = 0; mt < 4; mt++)
#pragma unroll
                for (int nt = 0; nt < 3; nt++)
                    mma16816h(acc[mt][nt], al[mt], bh[nt]);
        }

        CP_WAIT0();
        __syncthreads();
    }

    const int gid = lane >> 2, tig = lane & 3;
#pragma unroll
    for (int mt = 0; mt < 4; mt++) {
#pragma unroll
        for (int nt = 0; nt < 3; nt++) {
            const int col0 = wbase + 8 * nt;
            const int mat  = col0 >> 6;
            const int d0   = (col0 & 63) + 2 * tig;
            const float* bp = (mat == 0) ? bq : (mat == 1) ? bk : bv;
            const float b0v = bp[d0], b1v = bp[d0 + 1];
            const int row0 = m0 + 16 * mt + gid;
            float v00 = acc[mt][nt][0] + b0v, v01 = acc[mt][nt][1] + b1v;
            float v10 = acc[mt][nt][2] + b0v, v11 = acc[mt][nt][3] + b1v;
            if (mat == 0) {
                // fold score scale into q (exact *2^-3), split to fp16 hi/lo
                v00 *= 0.125f; v01 *= 0.125f; v10 *= 0.125f; v11 *= 0.125f;
                __half h00,l00,h01,l01,h10,l10,h11,l11;
                split_f16(v00, h00, l00); split_f16(v01, h01, l01);
                split_f16(v10, h10, l10); split_f16(v11, h11, l11);
                *(uint32_t*)&g_qhi[(size_t)row0 * DD + d0]       = pack_h2(h00, h01);
                *(uint32_t*)&g_qlo[(size_t)row0 * DD + d0]       = pack_h2(l00, l01);
                *(uint32_t*)&g_qhi[(size_t)(row0 + 8) * DD + d0] = pack_h2(h10, h11);
                *(uint32_t*)&g_qlo[(size_t)(row0 + 8) * DD + d0] = pack_h2(l10, l11);
            } else if (mat == 1) {
                *(uint32_t*)&g_kh[(size_t)row0 * DD + d0] =
                    pack_h2(__float2half_rn(v00), __float2half_rn(v01));
                *(uint32_t*)&g_kh[(size_t)(row0 + 8) * DD + d0] =
                    pack_h2(__float2half_rn(v10), __float2half_rn(v11));
            } else {
                const int bb = row0 >> 12, t = row0 & 4095;
                size_t r0o = ((size_t)bb * 64 + d0) * TT + t;
                size_t r1o = ((size_t)bb * 64 + d0 + 1) * TT + t;
                g_vth[r0o]     = __float2half_rn(v00);
                g_vth[r1o]     = __float2half_rn(v01);
                g_vth[r0o + 8] = __float2half_rn(v10);
                g_vth[r1o + 8] = __float2half_rn(v11);
            }
        }
    }
}

// ---------------------------------------------------------------------------
// Flash attention (R9 — verified): fp16 2-term S and PV, paired halves,
// double-buffered single-word K/V.
// ---------------------------------------------------------------------------
#define AH_STRIDE 49152
#define ATTN_SMEM (2*AH_STRIDE)   // 98304

DEVINL void stage_kv(uint32_t kdst, uint32_t vdst, int htid, int b, int t0) {
#pragma unroll
    for (int i = 0; i < 8; i++) {
        int u = htid + 128 * i;
        int mat = u >> 9, w = u & 511, r = w >> 3, cu = w & 7;
        const __half* src = mat
            ? g_vth + ((size_t)b * DD + r) * TT + t0 + cu * 8
            : g_kh  + (size_t)(b * TT + t0 + r) * DD + cu * 8;
        uint32_t dst = (mat ? vdst : kdst) + (uint32_t)r * 128
                     + (((uint32_t)cu * 16) ^ ((uint32_t)(r & 7) << 4));
        CP_ASYNC16(dst, src);
    }
}

__global__ __launch_bounds__(256, 1) void attn_mma(float* __restrict__ out)
{
    extern __shared__ __align__(1024) unsigned char sm[];
    const uint32_t sb = smem_u32(sm);
    const int tid  = threadIdx.x;
    const int warp = tid >> 5;
    const int lane = tid & 31;
    const int half = warp >> 2;
    const int wh   = warp & 3;
    const int htid = tid & 127;
    const int b    = blockIdx.y;
    const int qp   = blockIdx.x;
    const int qt   = half ? (63 - qp) : qp;
    const uint32_t hb = sb + (uint32_t)half * AH_STRIDE;
    const int tok0 = b * TT + qt * 64;
    const int nbid = half + 1;

    const int gid = lane >> 2, tig = lane & 3;
    const int rA = (lane & 7) | (((lane >> 3) & 1) << 3);
    const int uA = lane >> 4;
    const int rB = lane & 7;
    const int uB = (lane >> 3) & 1;
    const uint32_t swA = (uint32_t)(rA & 7) << 4;
    const uint32_t swB = (uint32_t)(rB) << 4;

#pragma unroll
    for (int i = 0; i < 8; i++) {
        int u = htid + 128 * i;
        int matq = u >> 9, r = (u >> 3) & 63, cu = u & 7;
        const __half* src = (matq ? g_qlo : g_qhi)
                          + (size_t)(tok0 + r) * DD + cu * 8;
        uint32_t dst = hb + matq * 8192 + (uint32_t)r * 128
                     + (((uint32_t)cu * 16) ^ ((uint32_t)(r & 7) << 4));
        CP_ASYNC16(dst, src);
    }
    stage_kv(hb + 16384, hb + 32768, htid, b, 0);
    CP_COMMIT();
    CP_WAIT0();
    NB_SYNC(nbid);

    uint32_t qh[4][4], ql[4][4];
#pragma unroll
    for (int kk = 0; kk < 4; kk++) {
        uint32_t ra = hb + (uint32_t)(wh * 16 + rA) * 128
                    + (((uint32_t)(2*kk + uA) * 16) ^ swA);
        ldsm_x4(qh[kk], ra);
        ldsm_x4(ql[kk], ra + 8192);
    }

    float oA[8][4];
#pragma unroll
    for (int nd = 0; nd < 8; nd++)
#pragma unroll
        for (int i = 0; i < 4; i++) oA[nd][i] = 0.f;
    float m0r = -3.0e38f, m1r = -3.0e38f, l0r = 0.f, l1r = 0.f;

    for (int j = 0; j <= qt; j++) {
        if (j) { CP_WAIT0(); NB_SYNC(nbid); }
        const uint32_t kbase = hb + 16384 + (uint32_t)(j & 1) * 8192;
        const uint32_t vbase = hb + 32768 + (uint32_t)(j & 1) * 8192;

        if (j < qt) {
            stage_kv(hb + 16384 + (uint32_t)((j + 1) & 1) * 8192,
                     hb + 32768 + (uint32_t)((j + 1) & 1) * 8192,
                     htid, b, (j + 1) * 64);
            CP_COMMIT();
        }

        float sA[8][4];
#pragma unroll
        for (int nt = 0; nt < 8; nt++)
#pragma unroll
            for (int i = 0; i < 4; i++) sA[nt][i] = 0.f;
#pragma unroll
        for (int kk = 0; kk < 4; kk++) {
            uint32_t bh[8][2];
#pragma unroll
            for (int nt = 0; nt < 8; nt++) {
                uint32_t rb = kbase + (uint32_t)(nt * 8 + rB) * 128
                            + (((uint32_t)(2*kk + uB) * 16) ^ swB);
                ldsm_x2(bh[nt], rb);
            }
#pragma unroll
            for (int nt = 0; nt < 8; nt++) mma16816h(sA[nt], qh[kk], bh[nt]);
#pragma unroll
            for (int nt = 0; nt < 8; nt++) mma16816h(sA[nt], ql[kk], bh[nt]);
        }

        if (j == qt) {
            const int r0 = qt * 64 + wh * 16 + gid, r1 = r0 + 8;
#pragma unroll
            for (int nt = 0; nt < 8; nt++) {
                int c0 = j * 64 + nt * 8 + 2 * tig;
                if (c0     > r0) sA[nt][0] = -1e30f;
                if (c0 + 1 > r0) sA[nt][1] = -1e30f;
                if (c0     > r1) sA[nt][2] = -1e30f;
                if (c0 + 1 > r1) sA[nt][3] = -1e30f;
            }
        }

        float mx0 = sA[0][0], mx1 = sA[0][2];
#pragma unroll
        for (int nt = 0; nt < 8; nt++) {
            mx0 = fmaxf(mx0, fmaxf(sA[nt][0], sA[nt][1]));
            mx1 = fmaxf(mx1, fmaxf(sA[nt][2], sA[nt][3]));
        }
        mx0 = fmaxf(mx0, __shfl_xor_sync(0xffffffffu, mx0, 1));
        mx0 = fmaxf(mx0, __shfl_xor_sync(0xffffffffu, mx0, 2));
        mx1 = fmaxf(mx1, __shfl_xor_sync(0xffffffffu, mx1, 1));
        mx1 = fmaxf(mx1, __shfl_xor_sync(0xffffffffu, mx1, 2));
        float mn0 = fmaxf(m0r, mx0), mn1 = fmaxf(m1r, mx1);
        float al0 = __expf(m0r - mn0), al1 = __expf(m1r - mn1);
        float ps0 = 0.f, ps1 = 0.f;
#pragma unroll
        for (int nt = 0; nt < 8; nt++) {
            sA[nt][0] = __expf(sA[nt][0] - mn0);
            sA[nt][1] = __expf(sA[nt][1] - mn0);
            sA[nt][2] = __expf(sA[nt][2] - mn1);
            sA[nt][3] = __expf(sA[nt][3] - mn1);
            ps0 += sA[nt][0] + sA[nt][1];
            ps1 += sA[nt][2] + sA[nt][3];
        }
        ps0 += __shfl_xor_sync(0xffffffffu, ps0, 1);
        ps0 += __shfl_xor_sync(0xffffffffu, ps0, 2);
        ps1 += __shfl_xor_sync(0xffffffffu, ps1, 1);
        ps1 += __shfl_xor_sync(0xffffffffu, ps1, 2);
        l0r = l0r * al0 + ps0;  m0r = mn0;
        l1r = l1r * al1 + ps1;  m1r = mn1;
#pragma unroll
        for (int nd = 0; nd < 8; nd++) {
            oA[nd][0] *= al0; oA[nd][1] *= al0;
            oA[nd][2] *= al1; oA[nd][3] *= al1;
        }

#pragma unroll
        for (int kk = 0; kk < 4; kk++) {
            uint32_t aphi[4], aplo[4];
            {
                __half h0,l0,h1,l1;
                split_f16(sA[2*kk][0], h0, l0);   split_f16(sA[2*kk][1], h1, l1);
                aphi[0] = pack_h2(h0, h1);        aplo[0] = pack_h2(l0, l1);
                split_f16(sA[2*kk][2], h0, l0);   split_f16(sA[2*kk][3], h1, l1);
                aphi[1] = pack_h2(h0, h1);        aplo[1] = pack_h2(l0, l1);
                split_f16(sA[2*kk+1][0], h0, l0); split_f16(sA[2*kk+1][1], h1, l1);
                aphi[2] = pack_h2(h0, h1);        aplo[2] = pack_h2(l0, l1);
                split_f16(sA[2*kk+1][2], h0, l0); split_f16(sA[2*kk+1][3], h1, l1);
                aphi[3] = pack_h2(h0, h1);        aplo[3] = pack_h2(l0, l1);
            }
            uint32_t vh[8][2];
#pragma unroll
            for (int nd = 0; nd < 8; nd++) {
                uint32_t rv = vbase + (uint32_t)(nd * 8 + rB) * 128
                            + (((uint32_t)(2*kk + uB) * 16) ^ swB);
                ldsm_x2(vh[nd], rv);
            }
#pragma unroll
            for (int nd = 0; nd < 8; nd++) mma16816h(oA[nd], aphi, vh[nd]);
#pragma unroll
            for (int nd = 0; nd < 8; nd++) mma16816h(oA[nd], aplo, vh[nd]);
        }
    }

    const float inv0 = 1.f / l0r, inv1 = 1.f / l1r;
    const size_t out0 = ((size_t)b * TT + qt * 64 + wh * 16 + gid) * DD;
    const size_t out1 = out0 + 8 * DD;
#pragma unroll
    for (int nd = 0; nd < 8; nd++) {
        const int d0 = nd * 8 + 2 * tig;
        *(float2*)&out[out0 + d0] = make_float2(oA[nd][0] * inv0, oA[nd][1] * inv0);
        *(float2*)&out[out1 + d0] = make_float2(oA[nd][2] * inv1, oA[nd][3] * inv1);
    }
}

// ---------------------------------------------------------------------------
extern "C" void kernel_launch(void* const* d_in, const int* in_sizes, int n_in,
                              void* d_out, int out_size)
{
    const float* X  = (const float*)d_in[0];
    const float* Wq = (const float*)d_in[1];
    const float* bq = (const float*)d_in[2];
    const float* Wk = (const float*)d_in[3];
    const float* bk = (const float*)d_in[4];
    const float* Wv = (const float*)d_in[5];
    const float* bv = (const float*)d_in[6];
    float* out = (float*)d_out;

    prep<<<8192 + 16, 256>>>(X, Wq, Wk, Wv);

    cudaFuncSetAttribute(qkv_mma, cudaFuncAttributeMaxDynamicSharedMemorySize, QKV_SMEM);
    qkv_mma<<<MM / 64, 256, QKV_SMEM>>>(bq, bk, bv);

    cudaFuncSetAttribute(attn_mma, cudaFuncAttributeMaxDynamicSharedMemorySize, ATTN_SMEM);
    attn_mma<<<dim3(32, BB), 256, ATTN_SMEM>>>(out);
}

// round 11
// speedup vs baseline: 1.7761x; 1.2476x over previous
#include <cuda_runtime.h>
#include <cuda_bf16.h>
#include <cuda_fp16.h>
#include <cstdint>
#include <math.h>

#define BB 4
#define TT 4096
#define EE 1024
#define DD 64
#define MM (BB*TT)

// ---------------------------------------------------------------------------
// Device scratch.  Q: fp16 hi/lo. K: single fp16. V: single fp16, transposed.
// ---------------------------------------------------------------------------
__device__ __half g_qhi[MM*DD];
__device__ __half g_qlo[MM*DD];
__device__ __half g_kh [MM*DD];
__device__ __half g_vth[MM*DD];

// W: single fp16, transposed (rows n = mat*64+d, 64 k per row), SW128/chunk
#define WCHUNK_BYTES (192*128)
__device__ unsigned char g_wh[16*WCHUNK_BYTES];

// X: single fp16, pre-swizzled [row][16 k-chunks][128 bytes]
__device__ unsigned char g_xh[(size_t)MM*16*128];

// ---------------------------------------------------------------------------
// Helpers
// ---------------------------------------------------------------------------
#define DEVINL __device__ __forceinline__

DEVINL uint32_t smem_u32(const void* p) {
    uint32_t a;
    asm("{ .reg .u64 t; cvta.to.shared.u64 t, %1; cvt.u32.u64 %0, t; }"
        : "=r"(a) : "l"(p));
    return a;
}

#define SWZ128(o) ((o) ^ (((o) >> 3) & 0x70))

#define CP_ASYNC16(dst, src) \
    asm volatile("cp.async.cg.shared.global [%0], [%1], 16;" \
                 :: "r"(dst), "l"(src) : "memory")
#define CP_COMMIT() asm volatile("cp.async.commit_group;" ::: "memory")
#define CP_WAIT0()  asm volatile("cp.async.wait_group 0;"  ::: "memory")

#define NB_SYNC(id) asm volatile("bar.sync %0, 128;" :: "r"(id) : "memory")

DEVINL uint32_t pack_h2(__half a, __half b) {
    return (uint32_t)__half_as_ushort(a) |
           ((uint32_t)__half_as_ushort(b) << 16);
}
DEVINL void split_f16(float x, __half& h, __half& l) {
    h = __float2half_rn(x);
    l = __float2half_rn(x - __half2float(h));
}

DEVINL void ldsm_x4(uint32_t r[4], uint32_t addr) {
    asm volatile("ldmatrix.sync.aligned.m8n8.x4.shared.b16 {%0,%1,%2,%3}, [%4];"
        : "=r"(r[0]), "=r"(r[1]), "=r"(r[2]), "=r"(r[3]) : "r"(addr));
}
DEVINL void ldsm_x2(uint32_t r[2], uint32_t addr) {
    asm volatile("ldmatrix.sync.aligned.m8n8.x2.shared.b16 {%0,%1}, [%2];"
        : "=r"(r[0]), "=r"(r[1]) : "r"(addr));
}
DEVINL void mma16816h(float c[4], const uint32_t a[4], const uint32_t b[2]) {
    asm volatile(
        "mma.sync.aligned.m16n8k16.row.col.f32.f16.f16.f32 "
        "{%0,%1,%2,%3}, {%4,%5,%6,%7}, {%8,%9}, {%0,%1,%2,%3};"
        : "+f"(c[0]), "+f"(c[1]), "+f"(c[2]), "+f"(c[3])
        : "r"(a[0]), "r"(a[1]), "r"(a[2]), "r"(a[3]), "r"(b[0]), "r"(b[1]));
}

// ---------------------------------------------------------------------------
// Merged prep: blocks < 8192 round X to fp16; rest W (single fp16, transposed).
// ---------------------------------------------------------------------------
__global__ __launch_bounds__(256) void prep(
    const float* __restrict__ X,
    const float* __restrict__ Wq, const float* __restrict__ Wk,
    const float* __restrict__ Wv)
{
    if (blockIdx.x < 8192) {
        const int u = blockIdx.x * 256 + threadIdx.x;
        const int row  = u >> 7;
        const int unit = u & 127;
        const int c    = unit >> 3;
        const int col8 = unit & 7;
        const float4 a = *(const float4*)&X[(size_t)row * EE + c * 64 + col8 * 8];
        const float4 b = *(const float4*)&X[(size_t)row * EE + c * 64 + col8 * 8 + 4];
        uint4 hh = make_uint4(
            pack_h2(__float2half_rn(a.x), __float2half_rn(a.y)),
            pack_h2(__float2half_rn(a.z), __float2half_rn(a.w)),
            pack_h2(__float2half_rn(b.x), __float2half_rn(b.y)),
            pack_h2(__float2half_rn(b.z), __float2half_rn(b.w)));
        size_t off = (((size_t)row * 16 + c) << 7)
                   + ((((uint32_t)col8 * 16) ^ ((uint32_t)(row & 7) << 4)));
        *(uint4*)(g_xh + off) = hh;
    } else {
        const int c = blockIdx.x - 8192;
        for (int it = threadIdx.x; it < 1536; it += 256) {
            int n = it % 192;
            int g = it / 192;
            int mat = n >> 6, d = n & 63;
            const float* Wm = (mat == 0) ? Wq : (mat == 1) ? Wk : Wv;
            int kk0 = g * 8;
            uint32_t hi[4];
#pragma unroll
            for (int j = 0; j < 4; j++) {
                __half h0 = __float2half_rn(Wm[(size_t)(c*64 + kk0 + 2*j    ) * 64 + d]);
                __half h1 = __float2half_rn(Wm[(size_t)(c*64 + kk0 + 2*j + 1) * 64 + d]);
                hi[j] = pack_h2(h0, h1);
            }
            uint32_t sw = SWZ128((uint32_t)n * 128 + (uint32_t)kk0 * 2);
            *(uint4*)(g_wh + (size_t)c * WCHUNK_BYTES + sw) = make_uint4(hi[0], hi[1], hi[2], hi[3]);
        }
    }
}

// ---------------------------------------------------------------------------
// QKV via mma.sync, pure fp16: acc += Xh . Wh.  CTA tile M=64, N=192,
// k-chunks of 64, double-buffered. Buffer: A 8K @0, B 24K @8192. Stride 32K.
// ---------------------------------------------------------------------------
#define QB_A    0
#define QB_B    8192
#define QB_STRIDE 32768
#define QKV_SMEM (2*QB_STRIDE)   // 65536

__global__ __launch_bounds__(256, 1) void qkv_mma(
    const float* __restrict__ bq, const float* __restrict__ bk,
    const float* __restrict__ bv)
{
    extern __shared__ __align__(1024) unsigned char sm[];
    const uint32_t sb = smem_u32(sm);
    const int tid  = threadIdx.x;
    const int warp = tid >> 5;
    const int lane = tid & 31;
    const int m0   = blockIdx.x * 64;
    const int wbase = warp * 24;

    const int rA = (lane & 7) | (((lane >> 3) & 1) << 3);
    const int uA = lane >> 4;
    const int rB = lane & 7;
    const int uB = (lane >> 3) & 1;
    const uint32_t swA = (uint32_t)(rA & 7) << 4;
    const uint32_t swB = (uint32_t)(rB & 7) << 4;

    float acc[4][3][4];
#pragma unroll
    for (int mt = 0; mt < 4; mt++)
#pragma unroll
        for (int nt = 0; nt < 3; nt++)
#pragma unroll
            for (int i = 0; i < 4; i++) acc[mt][nt][i] = 0.f;

    {
#pragma unroll
        for (int j = 0; j < 6; j++) {
            int f = tid + 256 * j;
            CP_ASYNC16(sb + QB_B + f * 16, g_wh + (size_t)f * 16);
        }
#pragma unroll
        for (int i = 0; i < 2; i++) {
            int w = tid + 256 * i;   // 0..511
            size_t src = (((size_t)(m0 + (w >> 3)) * 16) << 7) + (w & 7) * 16;
            CP_ASYNC16(sb + QB_A + (uint32_t)w * 16, g_xh + src);
        }
        CP_COMMIT();
        CP_WAIT0();
        __syncthreads();
    }

    for (int c = 0; c < 16; c++) {
        const uint32_t bufc = sb + (uint32_t)(c & 1) * QB_STRIDE;
        const uint32_t bufn = sb + (uint32_t)((c + 1) & 1) * QB_STRIDE;
        const bool hasNext = (c < 15);

        if (hasNext) {
            const unsigned char* wh = g_wh + (size_t)(c + 1) * WCHUNK_BYTES;
#pragma unroll
            for (int j = 0; j < 6; j++) {
                int f = tid + 256 * j;
                CP_ASYNC16(bufn + QB_B + f * 16, wh + (size_t)f * 16);
            }
#pragma unroll
            for (int i = 0; i < 2; i++) {
                int w = tid + 256 * i;
                size_t src = (((size_t)(m0 + (w >> 3)) * 16 + (c + 1)) << 7) + (w & 7) * 16;
                CP_ASYNC16(bufn + QB_A + (uint32_t)w * 16, g_xh + src);
            }
            CP_COMMIT();
        }

#pragma unroll
        for (int kk = 0; kk < 4; kk++) {
            uint32_t ah[4][4];
#pragma unroll
            for (int mt = 0; mt < 4; mt++) {
                uint32_t ra = bufc + QB_A + (uint32_t)(16*mt + rA) * 128
                            + (((uint32_t)(2*kk + uA) * 16) ^ swA);
                ldsm_x4(ah[mt], ra);
            }
            uint32_t bh[3][2];
#pragma unroll
            for (int nt = 0; nt < 3; nt++) {
                uint32_t rb = bufc + QB_B + (uint32_t)(wbase + 8*nt + rB) * 128
                            + (((uint32_t)(2*kk + uB) * 16) ^ swB);
                ldsm_x2(bh[nt], rb);
            }
#pragma unroll
            for (int mt = 0; mt < 4; mt++)
#pragma unroll
                for (int nt = 0; nt < 3; nt++)
                    mma16816h(acc[mt][nt], ah[mt], bh[nt]);
        }

        CP_WAIT0();
        __syncthreads();
    }

    const int gid = lane >> 2, tig = lane & 3;
#pragma unroll
    for (int mt = 0; mt < 4; mt++) {
#pragma unroll
        for (int nt = 0; nt < 3; nt++) {
            const int col0 = wbase + 8 * nt;
            const int mat  = col0 >> 6;
            const int d0   = (col0 & 63) + 2 * tig;
            const float* bp = (mat == 0) ? bq : (mat == 1) ? bk : bv;
            const float b0v = bp[d0], b1v = bp[d0 + 1];
            const int row0 = m0 + 16 * mt + gid;
            float v00 = acc[mt][nt][0] + b0v, v01 = acc[mt][nt][1] + b1v;
            float v10 = acc[mt][nt][2] + b0v, v11 = acc[mt][nt][3] + b1v;
            if (mat == 0) {
                // fold score scale into q (exact *2^-3), split to fp16 hi/lo
                v00 *= 0.125f; v01 *= 0.125f; v10 *= 0.125f; v11 *= 0.125f;
                __half h00,l00,h01,l01,h10,l10,h11,l11;
                split_f16(v00, h00, l00); split_f16(v01, h01, l01);
                split_f16(v10, h10, l10); split_f16(v11, h11, l11);
                *(uint32_t*)&g_qhi[(size_t)row0 * DD + d0]       = pack_h2(h00, h01);
                *(uint32_t*)&g_qlo[(size_t)row0 * DD + d0]       = pack_h2(l00, l01);
                *(uint32_t*)&g_qhi[(size_t)(row0 + 8) * DD + d0] = pack_h2(h10, h11);
                *(uint32_t*)&g_qlo[(size_t)(row0 + 8) * DD + d0] = pack_h2(l10, l11);
            } else if (mat == 1) {
                *(uint32_t*)&g_kh[(size_t)row0 * DD + d0] =
                    pack_h2(__float2half_rn(v00), __float2half_rn(v01));
                *(uint32_t*)&g_kh[(size_t)(row0 + 8) * DD + d0] =
                    pack_h2(__float2half_rn(v10), __float2half_rn(v11));
            } else {
                const int bb = row0 >> 12, t = row0 & 4095;
                size_t r0o = ((size_t)bb * 64 + d0) * TT + t;
                size_t r1o = ((size_t)bb * 64 + d0 + 1) * TT + t;
                g_vth[r0o]     = __float2half_rn(v00);
                g_vth[r1o]     = __float2half_rn(v01);
                g_vth[r0o + 8] = __float2half_rn(v10);
                g_vth[r1o + 8] = __float2half_rn(v11);
            }
        }
    }
}

// ---------------------------------------------------------------------------
// Flash attention: S = (qh+ql)·kh (2-term), PV = P̂·vh (single-term, P rounded
// to fp16). Paired halves, double-buffered single-word K/V.
// ---------------------------------------------------------------------------
#define AH_STRIDE 49152
#define ATTN_SMEM (2*AH_STRIDE)   // 98304

DEVINL void stage_kv(uint32_t kdst, uint32_t vdst, int htid, int b, int t0) {
#pragma unroll
    for (int i = 0; i < 8; i++) {
        int u = htid + 128 * i;
        int mat = u >> 9, w = u & 511, r = w >> 3, cu = w & 7;
        const __half* src = mat
            ? g_vth + ((size_t)b * DD + r) * TT + t0 + cu * 8
            : g_kh  + (size_t)(b * TT + t0 + r) * DD + cu * 8;
        uint32_t dst = (mat ? vdst : kdst) + (uint32_t)r * 128
                     + (((uint32_t)cu * 16) ^ ((uint32_t)(r & 7) << 4));
        CP_ASYNC16(dst, src);
    }
}

__global__ __launch_bounds__(256, 1) void attn_mma(float* __restrict__ out)
{
    extern __shared__ __align__(1024) unsigned char sm[];
    const uint32_t sb = smem_u32(sm);
    const int tid  = threadIdx.x;
    const int warp = tid >> 5;
    const int lane = tid & 31;
    const int half = warp >> 2;
    const int wh   = warp & 3;
    const int htid = tid & 127;
    const int b    = blockIdx.y;
    const int qp   = blockIdx.x;
    const int qt   = half ? (63 - qp) : qp;
    const uint32_t hb = sb + (uint32_t)half * AH_STRIDE;
    const int tok0 = b * TT + qt * 64;
    const int nbid = half + 1;

    const int gid = lane >> 2, tig = lane & 3;
    const int rA = (lane & 7) | (((lane >> 3) & 1) << 3);
    const int uA = lane >> 4;
    const int rB = lane & 7;
    const int uB = (lane >> 3) & 1;
    const uint32_t swA = (uint32_t)(rA & 7) << 4;
    const uint32_t swB = (uint32_t)(rB) << 4;

#pragma unroll
    for (int i = 0; i < 8; i++) {
        int u = htid + 128 * i;
        int matq = u >> 9, r = (u >> 3) & 63, cu = u & 7;
        const __half* src = (matq ? g_qlo : g_qhi)
                          + (size_t)(tok0 + r) * DD + cu * 8;
        uint32_t dst = hb + matq * 8192 + (uint32_t)r * 128
                     + (((uint32_t)cu * 16) ^ ((uint32_t)(r & 7) << 4));
        CP_ASYNC16(dst, src);
    }
    stage_kv(hb + 16384, hb + 32768, htid, b, 0);
    CP_COMMIT();
    CP_WAIT0();
    NB_SYNC(nbid);

    uint32_t qh[4][4], ql[4][4];
#pragma unroll
    for (int kk = 0; kk < 4; kk++) {
        uint32_t ra = hb + (uint32_t)(wh * 16 + rA) * 128
                    + (((uint32_t)(2*kk + uA) * 16) ^ swA);
        ldsm_x4(qh[kk], ra);
        ldsm_x4(ql[kk], ra + 8192);
    }

    float oA[8][4];
#pragma unroll
    for (int nd = 0; nd < 8; nd++)
#pragma unroll
        for (int i = 0; i < 4; i++) oA[nd][i] = 0.f;
    float m0r = -3.0e38f, m1r = -3.0e38f, l0r = 0.f, l1r = 0.f;

    for (int j = 0; j <= qt; j++) {
        if (j) { CP_WAIT0(); NB_SYNC(nbid); }
        const uint32_t kbase = hb + 16384 + (uint32_t)(j & 1) * 8192;
        const uint32_t vbase = hb + 32768 + (uint32_t)(j & 1) * 8192;

        if (j < qt) {
            stage_kv(hb + 16384 + (uint32_t)((j + 1) & 1) * 8192,
                     hb + 32768 + (uint32_t)((j + 1) & 1) * 8192,
                     htid, b, (j + 1) * 64);
            CP_COMMIT();
        }

        // ---- S = Q . K^T (2-term fp16) ----
        float sA[8][4];
#pragma unroll
        for (int nt = 0; nt < 8; nt++)
#pragma unroll
            for (int i = 0; i < 4; i++) sA[nt][i] = 0.f;
#pragma unroll
        for (int kk = 0; kk < 4; kk++) {
            uint32_t bh[8][2];
#pragma unroll
            for (int nt = 0; nt < 8; nt++) {
                uint32_t rb = kbase + (uint32_t)(nt * 8 + rB) * 128
                            + (((uint32_t)(2*kk + uB) * 16) ^ swB);
                ldsm_x2(bh[nt], rb);
            }
#pragma unroll
            for (int nt = 0; nt < 8; nt++) mma16816h(sA[nt], qh[kk], bh[nt]);
#pragma unroll
            for (int nt = 0; nt < 8; nt++) mma16816h(sA[nt], ql[kk], bh[nt]);
        }

        // ---- causal mask (diagonal tile only; scale folded into q) ----
        if (j == qt) {
            const int r0 = qt * 64 + wh * 16 + gid, r1 = r0 + 8;
#pragma unroll
            for (int nt = 0; nt < 8; nt++) {
                int c0 = j * 64 + nt * 8 + 2 * tig;
                if (c0     > r0) sA[nt][0] = -1e30f;
                if (c0 + 1 > r0) sA[nt][1] = -1e30f;
                if (c0     > r1) sA[nt][2] = -1e30f;
                if (c0 + 1 > r1) sA[nt][3] = -1e30f;
            }
        }

        // ---- online softmax ----
        float mx0 = sA[0][0], mx1 = sA[0][2];
#pragma unroll
        for (int nt = 0; nt < 8; nt++) {
            mx0 = fmaxf(mx0, fmaxf(sA[nt][0], sA[nt][1]));
            mx1 = fmaxf(mx1, fmaxf(sA[nt][2], sA[nt][3]));
        }
        mx0 = fmaxf(mx0, __shfl_xor_sync(0xffffffffu, mx0, 1));
        mx0 = fmaxf(mx0, __shfl_xor_sync(0xffffffffu, mx0, 2));
        mx1 = fmaxf(mx1, __shfl_xor_sync(0xffffffffu, mx1, 1));
        mx1 = fmaxf(mx1, __shfl_xor_sync(0xffffffffu, mx1, 2));
        float mn0 = fmaxf(m0r, mx0), mn1 = fmaxf(m1r, mx1);
        float al0 = __expf(m0r - mn0), al1 = __expf(m1r - mn1);
        float ps0 = 0.f, ps1 = 0.f;
#pragma unroll
        for (int nt = 0; nt < 8; nt++) {
            sA[nt][0] = __expf(sA[nt][0] - mn0);
            sA[nt][1] = __expf(sA[nt][1] - mn0);
            sA[nt][2] = __expf(sA[nt][2] - mn1);
            sA[nt][3] = __expf(sA[nt][3] - mn1);
            ps0 += sA[nt][0] + sA[nt][1];
            ps1 += sA[nt][2] + sA[nt][3];
        }
        ps0 += __shfl_xor_sync(0xffffffffu, ps0, 1);
        ps0 += __shfl_xor_sync(0xffffffffu, ps0, 2);
        ps1 += __shfl_xor_sync(0xffffffffu, ps1, 1);
        ps1 += __shfl_xor_sync(0xffffffffu, ps1, 2);
        l0r = l0r * al0 + ps0;  m0r = mn0;
        l1r = l1r * al1 + ps1;  m1r = mn1;
#pragma unroll
        for (int nd = 0; nd < 8; nd++) {
            oA[nd][0] *= al0; oA[nd][1] *= al0;
            oA[nd][2] *= al1; oA[nd][3] *= al1;
        }

        // ---- PV: O += round16(P) . Vh  (single-term) ----
#pragma unroll
        for (int kk = 0; kk < 4; kk++) {
            uint32_t ap[4];
            ap[0] = pack_h2(__float2half_rn(sA[2*kk][0]),   __float2half_rn(sA[2*kk][1]));
            ap[1] = pack_h2(__float2half_rn(sA[2*kk][2]),   __float2half_rn(sA[2*kk][3]));
            ap[2] = pack_h2(__float2half_rn(sA[2*kk+1][0]), __float2half_rn(sA[2*kk+1][1]));
            ap[3] = pack_h2(__float2half_rn(sA[2*kk+1][2]), __float2half_rn(sA[2*kk+1][3]));
            uint32_t vh[8][2];
#pragma unroll
            for (int nd = 0; nd < 8; nd++) {
                uint32_t rv = vbase + (uint32_t)(nd * 8 + rB) * 128
                            + (((uint32_t)(2*kk + uB) * 16) ^ swB);
                ldsm_x2(vh[nd], rv);
            }
#pragma unroll
            for (int nd = 0; nd < 8; nd++) mma16816h(oA[nd], ap, vh[nd]);
        }
    }

    const float inv0 = 1.f / l0r, inv1 = 1.f / l1r;
    const size_t out0 = ((size_t)b * TT + qt * 64 + wh * 16 + gid) * DD;
    const size_t out1 = out0 + 8 * DD;
#pragma unroll
    for (int nd = 0; nd < 8; nd++) {
        const int d0 = nd * 8 + 2 * tig;
        *(float2*)&out[out0 + d0] = make_float2(oA[nd][0] * inv0, oA[nd][1] * inv0);
        *(float2*)&out[out1 + d0] = make_float2(oA[nd][2] * inv1, oA[nd][3] * inv1);
    }
}

// ---------------------------------------------------------------------------
extern "C" void kernel_launch(void* const* d_in, const int* in_sizes, int n_in,
                              void* d_out, int out_size)
{
    const float* X  = (const float*)d_in[0];
    const float* Wq = (const float*)d_in[1];
    const float* bq = (const float*)d_in[2];
    const float* Wk = (const float*)d_in[3];
    const float* bk = (const float*)d_in[4];
    const float* Wv = (const float*)d_in[5];
    const float* bv = (const float*)d_in[6];
    float* out = (float*)d_out;

    prep<<<8192 + 16, 256>>>(X, Wq, Wk, Wv);

    cudaFuncSetAttribute(qkv_mma, cudaFuncAttributeMaxDynamicSharedMemorySize, QKV_SMEM);
    qkv_mma<<<MM / 64, 256, QKV_SMEM>>>(bq, bk, bv);

    cudaFuncSetAttribute(attn_mma, cudaFuncAttributeMaxDynamicSharedMemorySize, ATTN_SMEM);
    attn_mma<<<dim3(32, BB), 256, ATTN_SMEM>>>(out);
}

// round 12
// speedup vs baseline: 1.9071x; 1.0738x over previous
#include <cuda_runtime.h>
#include <cuda_bf16.h>
#include <cuda_fp16.h>
#include <cstdint>
#include <math.h>

#define BB 4
#define TT 4096
#define EE 1024
#define DD 64
#define MM (BB*TT)

// ---------------------------------------------------------------------------
// Device scratch.  Q, K: single fp16. V: single fp16, transposed.
// ---------------------------------------------------------------------------
__device__ __half g_qh [MM*DD];
__device__ __half g_kh [MM*DD];
__device__ __half g_vth[MM*DD];

// W: single fp16, transposed (rows n = mat*64+d, 64 k per row), SW128/chunk
#define WCHUNK_BYTES (192*128)
__device__ unsigned char g_wh[16*WCHUNK_BYTES];

// X: single fp16, pre-swizzled [row][16 k-chunks][128 bytes]
__device__ unsigned char g_xh[(size_t)MM*16*128];

// ---------------------------------------------------------------------------
// Helpers
// ---------------------------------------------------------------------------
#define DEVINL __device__ __forceinline__

DEVINL uint32_t smem_u32(const void* p) {
    uint32_t a;
    asm("{ .reg .u64 t; cvta.to.shared.u64 t, %1; cvt.u32.u64 %0, t; }"
        : "=r"(a) : "l"(p));
    return a;
}

#define SWZ128(o) ((o) ^ (((o) >> 3) & 0x70))

#define CP_ASYNC16(dst, src) \
    asm volatile("cp.async.cg.shared.global [%0], [%1], 16;" \
                 :: "r"(dst), "l"(src) : "memory")
#define CP_COMMIT() asm volatile("cp.async.commit_group;" ::: "memory")
#define CP_WAIT0()  asm volatile("cp.async.wait_group 0;"  ::: "memory")

#define NB_SYNC(id) asm volatile("bar.sync %0, 128;" :: "r"(id) : "memory")

DEVINL uint32_t pack_h2(__half a, __half b) {
    return (uint32_t)__half_as_ushort(a) |
           ((uint32_t)__half_as_ushort(b) << 16);
}

DEVINL void ldsm_x4(uint32_t r[4], uint32_t addr) {
    asm volatile("ldmatrix.sync.aligned.m8n8.x4.shared.b16 {%0,%1,%2,%3}, [%4];"
        : "=r"(r[0]), "=r"(r[1]), "=r"(r[2]), "=r"(r[3]) : "r"(addr));
}
DEVINL void ldsm_x2(uint32_t r[2], uint32_t addr) {
    asm volatile("ldmatrix.sync.aligned.m8n8.x2.shared.b16 {%0,%1}, [%2];"
        : "=r"(r[0]), "=r"(r[1]) : "r"(addr));
}
DEVINL void mma16816h(float c[4], const uint32_t a[4], const uint32_t b[2]) {
    asm volatile(
        "mma.sync.aligned.m16n8k16.row.col.f32.f16.f16.f32 "
        "{%0,%1,%2,%3}, {%4,%5,%6,%7}, {%8,%9}, {%0,%1,%2,%3};"
        : "+f"(c[0]), "+f"(c[1]), "+f"(c[2]), "+f"(c[3])
        : "r"(a[0]), "r"(a[1]), "r"(a[2]), "r"(a[3]), "r"(b[0]), "r"(b[1]));
}

// ---------------------------------------------------------------------------
// Merged prep: blocks < 8192 round X to fp16; rest W (single fp16, transposed).
// ---------------------------------------------------------------------------
__global__ __launch_bounds__(256) void prep(
    const float* __restrict__ X,
    const float* __restrict__ Wq, const float* __restrict__ Wk,
    const float* __restrict__ Wv)
{
    if (blockIdx.x < 8192) {
        const int u = blockIdx.x * 256 + threadIdx.x;
        const int row  = u >> 7;
        const int unit = u & 127;
        const int c    = unit >> 3;
        const int col8 = unit & 7;
        const float4 a = *(const float4*)&X[(size_t)row * EE + c * 64 + col8 * 8];
        const float4 b = *(const float4*)&X[(size_t)row * EE + c * 64 + col8 * 8 + 4];
        uint4 hh = make_uint4(
            pack_h2(__float2half_rn(a.x), __float2half_rn(a.y)),
            pack_h2(__float2half_rn(a.z), __float2half_rn(a.w)),
            pack_h2(__float2half_rn(b.x), __float2half_rn(b.y)),
            pack_h2(__float2half_rn(b.z), __float2half_rn(b.w)));
        size_t off = (((size_t)row * 16 + c) << 7)
                   + ((((uint32_t)col8 * 16) ^ ((uint32_t)(row & 7) << 4)));
        *(uint4*)(g_xh + off) = hh;
    } else {
        const int c = blockIdx.x - 8192;
        for (int it = threadIdx.x; it < 1536; it += 256) {
            int n = it % 192;
            int g = it / 192;
            int mat = n >> 6, d = n & 63;
            const float* Wm = (mat == 0) ? Wq : (mat == 1) ? Wk : Wv;
            int kk0 = g * 8;
            uint32_t hi[4];
#pragma unroll
            for (int j = 0; j < 4; j++) {
                __half h0 = __float2half_rn(Wm[(size_t)(c*64 + kk0 + 2*j    ) * 64 + d]);
                __half h1 = __float2half_rn(Wm[(size_t)(c*64 + kk0 + 2*j + 1) * 64 + d]);
                hi[j] = pack_h2(h0, h1);
            }
            uint32_t sw = SWZ128((uint32_t)n * 128 + (uint32_t)kk0 * 2);
            *(uint4*)(g_wh + (size_t)c * WCHUNK_BYTES + sw) = make_uint4(hi[0], hi[1], hi[2], hi[3]);
        }
    }
}

// ---------------------------------------------------------------------------
// QKV via mma.sync, pure fp16: acc += Xh . Wh.  CTA tile M=64, N=192,
// k-chunks of 64, double-buffered.
// ---------------------------------------------------------------------------
#define QB_A    0
#define QB_B    8192
#define QB_STRIDE 32768
#define QKV_SMEM (2*QB_STRIDE)   // 65536

__global__ __launch_bounds__(256, 1) void qkv_mma(
    const float* __restrict__ bq, const float* __restrict__ bk,
    const float* __restrict__ bv)
{
    extern __shared__ __align__(1024) unsigned char sm[];
    const uint32_t sb = smem_u32(sm);
    const int tid  = threadIdx.x;
    const int warp = tid >> 5;
    const int lane = tid & 31;
    const int m0   = blockIdx.x * 64;
    const int wbase = warp * 24;

    const int rA = (lane & 7) | (((lane >> 3) & 1) << 3);
    const int uA = lane >> 4;
    const int rB = lane & 7;
    const int uB = (lane >> 3) & 1;
    const uint32_t swA = (uint32_t)(rA & 7) << 4;
    const uint32_t swB = (uint32_t)(rB & 7) << 4;

    float acc[4][3][4];
#pragma unroll
    for (int mt = 0; mt < 4; mt++)
#pragma unroll
        for (int nt = 0; nt < 3; nt++)
#pragma unroll
            for (int i = 0; i < 4; i++) acc[mt][nt][i] = 0.f;

    {
#pragma unroll
        for (int j = 0; j < 6; j++) {
            int f = tid + 256 * j;
            CP_ASYNC16(sb + QB_B + f * 16, g_wh + (size_t)f * 16);
        }
#pragma unroll
        for (int i = 0; i < 2; i++) {
            int w = tid + 256 * i;
            size_t src = (((size_t)(m0 + (w >> 3)) * 16) << 7) + (w & 7) * 16;
            CP_ASYNC16(sb + QB_A + (uint32_t)w * 16, g_xh + src);
        }
        CP_COMMIT();
        CP_WAIT0();
        __syncthreads();
    }

    for (int c = 0; c < 16; c++) {
        const uint32_t bufc = sb + (uint32_t)(c & 1) * QB_STRIDE;
        const uint32_t bufn = sb + (uint32_t)((c + 1) & 1) * QB_STRIDE;
        const bool hasNext = (c < 15);

        if (hasNext) {
            const unsigned char* wh = g_wh + (size_t)(c + 1) * WCHUNK_BYTES;
#pragma unroll
            for (int j = 0; j < 6; j++) {
                int f = tid + 256 * j;
                CP_ASYNC16(bufn + QB_B + f * 16, wh + (size_t)f * 16);
            }
#pragma unroll
            for (int i = 0; i < 2; i++) {
                int w = tid + 256 * i;
                size_t src = (((size_t)(m0 + (w >> 3)) * 16 + (c + 1)) << 7) + (w & 7) * 16;
                CP_ASYNC16(bufn + QB_A + (uint32_t)w * 16, g_xh + src);
            }
            CP_COMMIT();
        }

#pragma unroll
        for (int kk = 0; kk < 4; kk++) {
            uint32_t ah[4][4];
#pragma unroll
            for (int mt = 0; mt < 4; mt++) {
                uint32_t ra = bufc + QB_A + (uint32_t)(16*mt + rA) * 128
                            + (((uint32_t)(2*kk + uA) * 16) ^ swA);
                ldsm_x4(ah[mt], ra);
            }
            uint32_t bh[3][2];
#pragma unroll
            for (int nt = 0; nt < 3; nt++) {
                uint32_t rb = bufc + QB_B + (uint32_t)(wbase + 8*nt + rB) * 128
                            + (((uint32_t)(2*kk + uB) * 16) ^ swB);
                ldsm_x2(bh[nt], rb);
            }
#pragma unroll
            for (int mt = 0; mt < 4; mt++)
#pragma unroll
                for (int nt = 0; nt < 3; nt++)
                    mma16816h(acc[mt][nt], ah[mt], bh[nt]);
        }

        CP_WAIT0();
        __syncthreads();
    }

    const int gid = lane >> 2, tig = lane & 3;
#pragma unroll
    for (int mt = 0; mt < 4; mt++) {
#pragma unroll
        for (int nt = 0; nt < 3; nt++) {
            const int col0 = wbase + 8 * nt;
            const int mat  = col0 >> 6;
            const int d0   = (col0 & 63) + 2 * tig;
            const float* bp = (mat == 0) ? bq : (mat == 1) ? bk : bv;
            const float b0v = bp[d0], b1v = bp[d0 + 1];
            const int row0 = m0 + 16 * mt + gid;
            float v00 = acc[mt][nt][0] + b0v, v01 = acc[mt][nt][1] + b1v;
            float v10 = acc[mt][nt][2] + b0v, v11 = acc[mt][nt][3] + b1v;
            if (mat == 0) {
                // fold score scale into q (exact *2^-3), round to fp16
                v00 *= 0.125f; v01 *= 0.125f; v10 *= 0.125f; v11 *= 0.125f;
                *(uint32_t*)&g_qh[(size_t)row0 * DD + d0] =
                    pack_h2(__float2half_rn(v00), __float2half_rn(v01));
                *(uint32_t*)&g_qh[(size_t)(row0 + 8) * DD + d0] =
                    pack_h2(__float2half_rn(v10), __float2half_rn(v11));
            } else if (mat == 1) {
                *(uint32_t*)&g_kh[(size_t)row0 * DD + d0] =
                    pack_h2(__float2half_rn(v00), __float2half_rn(v01));
                *(uint32_t*)&g_kh[(size_t)(row0 + 8) * DD + d0] =
                    pack_h2(__float2half_rn(v10), __float2half_rn(v11));
            } else {
                const int bb = row0 >> 12, t = row0 & 4095;
                size_t r0o = ((size_t)bb * 64 + d0) * TT + t;
                size_t r1o = ((size_t)bb * 64 + d0 + 1) * TT + t;
                g_vth[r0o]     = __float2half_rn(v00);
                g_vth[r1o]     = __float2half_rn(v01);
                g_vth[r0o + 8] = __float2half_rn(v10);
                g_vth[r1o + 8] = __float2half_rn(v11);
            }
        }
    }
}

// ---------------------------------------------------------------------------
// Flash attention, pure fp16 operands: S = qh·kh, PV = round16(P)·vh.
// Paired halves, double-buffered single-word K/V.
// Per half: Q 8K @0, K stages @8192 (2x8K), V stages @24576 (2x8K).
// ---------------------------------------------------------------------------
#define AH_STRIDE 40960
#define ATTN_SMEM (2*AH_STRIDE)   // 81920

DEVINL void stage_kv(uint32_t kdst, uint32_t vdst, int htid, int b, int t0) {
#pragma unroll
    for (int i = 0; i < 8; i++) {
        int u = htid + 128 * i;
        int mat = u >> 9, w = u & 511, r = w >> 3, cu = w & 7;
        const __half* src = mat
            ? g_vth + ((size_t)b * DD + r) * TT + t0 + cu * 8
            : g_kh  + (size_t)(b * TT + t0 + r) * DD + cu * 8;
        uint32_t dst = (mat ? vdst : kdst) + (uint32_t)r * 128
                     + (((uint32_t)cu * 16) ^ ((uint32_t)(r & 7) << 4));
        CP_ASYNC16(dst, src);
    }
}

__global__ __launch_bounds__(256, 1) void attn_mma(float* __restrict__ out)
{
    extern __shared__ __align__(1024) unsigned char sm[];
    const uint32_t sb = smem_u32(sm);
    const int tid  = threadIdx.x;
    const int warp = tid >> 5;
    const int lane = tid & 31;
    const int half = warp >> 2;
    const int wh   = warp & 3;
    const int htid = tid & 127;
    const int b    = blockIdx.y;
    const int qp   = blockIdx.x;
    const int qt   = half ? (63 - qp) : qp;
    const uint32_t hb = sb + (uint32_t)half * AH_STRIDE;
    const int tok0 = b * TT + qt * 64;
    const int nbid = half + 1;

    const int gid = lane >> 2, tig = lane & 3;
    const int rA = (lane & 7) | (((lane >> 3) & 1) << 3);
    const int uA = lane >> 4;
    const int rB = lane & 7;
    const int uB = (lane >> 3) & 1;
    const uint32_t swA = (uint32_t)(rA & 7) << 4;
    const uint32_t swB = (uint32_t)(rB) << 4;

    // ---- stage Q + KV tile 0 ----
#pragma unroll
    for (int i = 0; i < 4; i++) {
        int u = htid + 128 * i;                // 0..511
        int r = u >> 3, cu = u & 7;
        const __half* src = g_qh + (size_t)(tok0 + r) * DD + cu * 8;
        uint32_t dst = hb + (uint32_t)r * 128
                     + (((uint32_t)cu * 16) ^ ((uint32_t)(r & 7) << 4));
        CP_ASYNC16(dst, src);
    }
    stage_kv(hb + 8192, hb + 24576, htid, b, 0);
    CP_COMMIT();
    CP_WAIT0();
    NB_SYNC(nbid);

    uint32_t qh[4][4];
#pragma unroll
    for (int kk = 0; kk < 4; kk++) {
        uint32_t ra = hb + (uint32_t)(wh * 16 + rA) * 128
                    + (((uint32_t)(2*kk + uA) * 16) ^ swA);
        ldsm_x4(qh[kk], ra);
    }

    float oA[8][4];
#pragma unroll
    for (int nd = 0; nd < 8; nd++)
#pragma unroll
        for (int i = 0; i < 4; i++) oA[nd][i] = 0.f;
    float m0r = -3.0e38f, m1r = -3.0e38f, l0r = 0.f, l1r = 0.f;

    for (int j = 0; j <= qt; j++) {
        if (j) { CP_WAIT0(); NB_SYNC(nbid); }
        const uint32_t kbase = hb + 8192  + (uint32_t)(j & 1) * 8192;
        const uint32_t vbase = hb + 24576 + (uint32_t)(j & 1) * 8192;

        if (j < qt) {
            stage_kv(hb + 8192  + (uint32_t)((j + 1) & 1) * 8192,
                     hb + 24576 + (uint32_t)((j + 1) & 1) * 8192,
                     htid, b, (j + 1) * 64);
            CP_COMMIT();
        }

        // ---- S = Q . K^T (single-term fp16) ----
        float sA[8][4];
#pragma unroll
        for (int nt = 0; nt < 8; nt++)
#pragma unroll
            for (int i = 0; i < 4; i++) sA[nt][i] = 0.f;
#pragma unroll
        for (int kk = 0; kk < 4; kk++) {
            uint32_t bh[8][2];
#pragma unroll
            for (int nt = 0; nt < 8; nt++) {
                uint32_t rb = kbase + (uint32_t)(nt * 8 + rB) * 128
                            + (((uint32_t)(2*kk + uB) * 16) ^ swB);
                ldsm_x2(bh[nt], rb);
            }
#pragma unroll
            for (int nt = 0; nt < 8; nt++) mma16816h(sA[nt], qh[kk], bh[nt]);
        }

        // ---- causal mask (diagonal tile only; scale folded into q) ----
        if (j == qt) {
            const int r0 = qt * 64 + wh * 16 + gid, r1 = r0 + 8;
#pragma unroll
            for (int nt = 0; nt < 8; nt++) {
                int c0 = j * 64 + nt * 8 + 2 * tig;
                if (c0     > r0) sA[nt][0] = -1e30f;
                if (c0 + 1 > r0) sA[nt][1] = -1e30f;
                if (c0     > r1) sA[nt][2] = -1e30f;
                if (c0 + 1 > r1) sA[nt][3] = -1e30f;
            }
        }

        // ---- online softmax ----
        float mx0 = sA[0][0], mx1 = sA[0][2];
#pragma unroll
        for (int nt = 0; nt < 8; nt++) {
            mx0 = fmaxf(mx0, fmaxf(sA[nt][0], sA[nt][1]));
            mx1 = fmaxf(mx1, fmaxf(sA[nt][2], sA[nt][3]));
        }
        mx0 = fmaxf(mx0, __shfl_xor_sync(0xffffffffu, mx0, 1));
        mx0 = fmaxf(mx0, __shfl_xor_sync(0xffffffffu, mx0, 2));
        mx1 = fmaxf(mx1, __shfl_xor_sync(0xffffffffu, mx1, 1));
        mx1 = fmaxf(mx1, __shfl_xor_sync(0xffffffffu, mx1, 2));
        float mn0 = fmaxf(m0r, mx0), mn1 = fmaxf(m1r, mx1);
        float al0 = __expf(m0r - mn0), al1 = __expf(m1r - mn1);
        float ps0 = 0.f, ps1 = 0.f;
#pragma unroll
        for (int nt = 0; nt < 8; nt++) {
            sA[nt][0] = __expf(sA[nt][0] - mn0);
            sA[nt][1] = __expf(sA[nt][1] - mn0);
            sA[nt][2] = __expf(sA[nt][2] - mn1);
            sA[nt][3] = __expf(sA[nt][3] - mn1);
            ps0 += sA[nt][0] + sA[nt][1];
            ps1 += sA[nt][2] + sA[nt][3];
        }
        ps0 += __shfl_xor_sync(0xffffffffu, ps0, 1);
        ps0 += __shfl_xor_sync(0xffffffffu, ps0, 2);
        ps1 += __shfl_xor_sync(0xffffffffu, ps1, 1);
        ps1 += __shfl_xor_sync(0xffffffffu, ps1, 2);
        l0r = l0r * al0 + ps0;  m0r = mn0;
        l1r = l1r * al1 + ps1;  m1r = mn1;
#pragma unroll
        for (int nd = 0; nd < 8; nd++) {
            oA[nd][0] *= al0; oA[nd][1] *= al0;
            oA[nd][2] *= al1; oA[nd][3] *= al1;
        }

        // ---- PV: O += round16(P) . Vh ----
#pragma unroll
        for (int kk = 0; kk < 4; kk++) {
            uint32_t ap[4];
            ap[0] = pack_h2(__float2half_rn(sA[2*kk][0]),   __float2half_rn(sA[2*kk][1]));
            ap[1] = pack_h2(__float2half_rn(sA[2*kk][2]),   __float2half_rn(sA[2*kk][3]));
            ap[2] = pack_h2(__float2half_rn(sA[2*kk+1][0]), __float2half_rn(sA[2*kk+1][1]));
            ap[3] = pack_h2(__float2half_rn(sA[2*kk+1][2]), __float2half_rn(sA[2*kk+1][3]));
            uint32_t vh[8][2];
#pragma unroll
            for (int nd = 0; nd < 8; nd++) {
                uint32_t rv = vbase + (uint32_t)(nd * 8 + rB) * 128
                            + (((uint32_t)(2*kk + uB) * 16) ^ swB);
                ldsm_x2(vh[nd], rv);
            }
#pragma unroll
            for (int nd = 0; nd < 8; nd++) mma16816h(oA[nd], ap, vh[nd]);
        }
    }

    const float inv0 = 1.f / l0r, inv1 = 1.f / l1r;
    const size_t out0 = ((size_t)b * TT + qt * 64 + wh * 16 + gid) * DD;
    const size_t out1 = out0 + 8 * DD;
#pragma unroll
    for (int nd = 0; nd < 8; nd++) {
        const int d0 = nd * 8 + 2 * tig;
        *(float2*)&out[out0 + d0] = make_float2(oA[nd][0] * inv0, oA[nd][1] * inv0);
        *(float2*)&out[out1 + d0] = make_float2(oA[nd][2] * inv1, oA[nd][3] * inv1);
    }
}

// ---------------------------------------------------------------------------
extern "C" void kernel_launch(void* const* d_in, const int* in_sizes, int n_in,
                              void* d_out, int out_size)
{
    const float* X  = (const float*)d_in[0];
    const float* Wq = (const float*)d_in[1];
    const float* bq = (const float*)d_in[2];
    const float* Wk = (const float*)d_in[3];
    const float* bk = (const float*)d_in[4];
    const float* Wv = (const float*)d_in[5];
    const float* bv = (const float*)d_in[6];
    float* out = (float*)d_out;

    prep<<<8192 + 16, 256>>>(X, Wq, Wk, Wv);

    cudaFuncSetAttribute(qkv_mma, cudaFuncAttributeMaxDynamicSharedMemorySize, QKV_SMEM);
    qkv_mma<<<MM / 64, 256, QKV_SMEM>>>(bq, bk, bv);

    cudaFuncSetAttribute(attn_mma, cudaFuncAttributeMaxDynamicSharedMemorySize, ATTN_SMEM);
    attn_mma<<<dim3(32, BB), 256, ATTN_SMEM>>>(out);
}